// round 8
// baseline (speedup 1.0000x reference)
#include <cuda_runtime.h>
#include <cuda_bf16.h>
#include <math.h>
#include <stdint.h>

#define HIDDEN 2048
#define HEADS 16
#define HD 128
#define SEQL 2048
#define NBATCH 2
#define MROWS (NBATCH * SEQL) // 4096
#define KDIM 2048

// ---------------------------------------------------------------------------
// Scratch: __device__ globals (no cudaMalloc allowed)
// ---------------------------------------------------------------------------
__device__ float g_q[(size_t)MROWS * HIDDEN];
__device__ float g_k[(size_t)MROWS * HIDDEN];
__device__ float g_v[(size_t)MROWS * HIDDEN];
__device__ float g_o[(size_t)MROWS * HIDDEN];

__device__ __nv_bfloat16 g_xh[(size_t)MROWS * HIDDEN];
__device__ __nv_bfloat16 g_xl[(size_t)MROWS * HIDDEN];
__device__ __nv_bfloat16 g_oh[(size_t)MROWS * HIDDEN];
__device__ __nv_bfloat16 g_ol[(size_t)MROWS * HIDDEN];
__device__ __nv_bfloat16 g_wqh[(size_t)HIDDEN * HIDDEN];
__device__ __nv_bfloat16 g_wql[(size_t)HIDDEN * HIDDEN];
__device__ __nv_bfloat16 g_wkh[(size_t)HIDDEN * HIDDEN];
__device__ __nv_bfloat16 g_wkl[(size_t)HIDDEN * HIDDEN];
__device__ __nv_bfloat16 g_wvh[(size_t)HIDDEN * HIDDEN];
__device__ __nv_bfloat16 g_wvl[(size_t)HIDDEN * HIDDEN];
__device__ __nv_bfloat16 g_woh[(size_t)HIDDEN * HIDDEN];
__device__ __nv_bfloat16 g_wol[(size_t)HIDDEN * HIDDEN];

// bf16 split Q/K (post-RoPE) and transposed V for flash
__device__ __nv_bfloat16 g_qh[(size_t)MROWS * HIDDEN];
__device__ __nv_bfloat16 g_ql[(size_t)MROWS * HIDDEN];
__device__ __nv_bfloat16 g_kh[(size_t)MROWS * HIDDEN];
__device__ __nv_bfloat16 g_kl[(size_t)MROWS * HIDDEN];
__device__ __nv_bfloat16 g_vth[(size_t)MROWS * HIDDEN];
__device__ __nv_bfloat16 g_vtl[(size_t)MROWS * HIDDEN];

// ---------------------------------------------------------------------------
__device__ __forceinline__ void mma16816(float* c, const uint32_t* a, const uint32_t* b)
{
    asm volatile(
        "mma.sync.aligned.m16n8k16.row.col.f32.bf16.bf16.f32 "
        "{%0,%1,%2,%3}, {%4,%5,%6,%7}, {%8,%9}, {%0,%1,%2,%3};"
        : "+f"(c[0]), "+f"(c[1]), "+f"(c[2]), "+f"(c[3])
        : "r"(a[0]), "r"(a[1]), "r"(a[2]), "r"(a[3]), "r"(b[0]), "r"(b[1]));
}

#define LDSM4(r0, r1, r2, r3, addr) \
    asm volatile("ldmatrix.sync.aligned.m8n8.x4.shared.b16 {%0,%1,%2,%3}, [%4];" \
                 : "=r"(r0), "=r"(r1), "=r"(r2), "=r"(r3) : "r"(addr))

__device__ __forceinline__ void cpasync16(uint32_t saddr, const void* g)
{
    asm volatile("cp.async.cg.shared.global [%0], [%1], 16;" :: "r"(saddr), "l"(g));
}

// ---------------------------------------------------------------------------
// Split fp32 -> (bf16 hi, bf16 lo) elementwise, vectorized x4
// ---------------------------------------------------------------------------
__global__ void split_kernel(const float4* __restrict__ a,
                             __nv_bfloat16* __restrict__ hi,
                             __nv_bfloat16* __restrict__ lo, int n4)
{
    int i = blockIdx.x * blockDim.x + threadIdx.x;
    if (i >= n4) return;
    float4 v = a[i];
    __nv_bfloat16 h0 = __float2bfloat16(v.x);
    __nv_bfloat16 h1 = __float2bfloat16(v.y);
    __nv_bfloat16 h2 = __float2bfloat16(v.z);
    __nv_bfloat16 h3 = __float2bfloat16(v.w);
    __nv_bfloat16 l0 = __float2bfloat16(v.x - __bfloat162float(h0));
    __nv_bfloat16 l1 = __float2bfloat16(v.y - __bfloat162float(h1));
    __nv_bfloat16 l2 = __float2bfloat16(v.z - __bfloat162float(h2));
    __nv_bfloat16 l3 = __float2bfloat16(v.w - __bfloat162float(h3));
    ushort4 hv, lv;
    hv.x = __bfloat16_as_ushort(h0); hv.y = __bfloat16_as_ushort(h1);
    hv.z = __bfloat16_as_ushort(h2); hv.w = __bfloat16_as_ushort(h3);
    lv.x = __bfloat16_as_ushort(l0); lv.y = __bfloat16_as_ushort(l1);
    lv.z = __bfloat16_as_ushort(l2); lv.w = __bfloat16_as_ushort(l3);
    *(ushort4*)(hi + (size_t)i * 4) = hv;
    *(ushort4*)(lo + (size_t)i * 4) = lv;
}

// ---------------------------------------------------------------------------
// Fused bf16x3 GEMM, single K pass, cp.async 3-stage pipeline, ldmatrix frags.
// C = Ah@Bh^T + Ah@Bl^T + Al@Bh^T.  BM=128 BN=128 BK=32, 256 thr (8 warps).
// smem per stage: Ah|Al|Bh|Bl tiles of 128 rows x 40 bf16 (80B padded rows).
// ---------------------------------------------------------------------------
#define GBM 128
#define GBN 128
#define GBK 32
#define LDS_W 40
#define NSTAGE 3
#define STAGE_B 40960               // 4 tiles * 128*40*2 bytes
#define TILE_B 10240                // one tile bytes
#define GEMM_NC (KDIM / GBK)        // 64

__global__ __launch_bounds__(256, 1) void gemm3_kernel(
    const __nv_bfloat16* __restrict__ Ah, const __nv_bfloat16* __restrict__ Al,
    const __nv_bfloat16* __restrict__ Bh, const __nv_bfloat16* __restrict__ Bl,
    float* __restrict__ C)
{
    extern __shared__ char gsm[];
    const uint32_t sbase = (uint32_t)__cvta_generic_to_shared(gsm);

    const int tid = threadIdx.x;
    const int lane = tid & 31;
    const int wid = tid >> 5;
    const int wm = (wid & 3) * 32;
    const int wn = (wid >> 2) * 64;
    const int bm = blockIdx.y * GBM;
    const int bn = blockIdx.x * GBN;
    const int lrow = lane & 15;          // ldmatrix row within 16
    const int lcolsel = (lane >> 4) * 8; // ldmatrix col half

    float acc[2][8][4];
#pragma unroll
    for (int i = 0; i < 2; i++)
#pragma unroll
        for (int j = 0; j < 8; j++)
#pragma unroll
            for (int r = 0; r < 4; r++) acc[i][j][r] = 0.f;

    auto issue = [&](int c) {
        const int k0 = c * GBK;
        const uint32_t sb = sbase + (uint32_t)(c % NSTAGE) * STAGE_B;
#pragma unroll
        for (int j = 0; j < 2; j++) {
            const int id = tid + j * 256;
            const int r = id >> 2, c8 = (id & 3) * 8;
            const size_t ga = (size_t)(bm + r) * KDIM + k0 + c8;
            const size_t gb = (size_t)(bn + r) * KDIM + k0 + c8;
            const uint32_t so = (uint32_t)(r * LDS_W + c8) * 2;
            cpasync16(sb + so, Ah + ga);
            cpasync16(sb + TILE_B + so, Al + ga);
            cpasync16(sb + 2 * TILE_B + so, Bh + gb);
            cpasync16(sb + 3 * TILE_B + so, Bl + gb);
        }
        asm volatile("cp.async.commit_group;" ::: "memory");
    };

    issue(0);
    issue(1);

    for (int c = 0; c < GEMM_NC; c++) {
        if (c + 2 < GEMM_NC)
            asm volatile("cp.async.wait_group 1;" ::: "memory");
        else
            asm volatile("cp.async.wait_group 0;" ::: "memory");
        __syncthreads();
        if (c + 2 < GEMM_NC) issue(c + 2);

        const uint32_t sb = sbase + (uint32_t)(c % NSTAGE) * STAGE_B;
#pragma unroll
        for (int kk = 0; kk < GBK; kk += 16) {
            uint32_t ah[2][4], al[2][4];
#pragma unroll
            for (int mt = 0; mt < 2; mt++) {
                const uint32_t ra = sb + (uint32_t)((wm + mt * 16 + lrow) * LDS_W + kk + lcolsel) * 2;
                LDSM4(ah[mt][0], ah[mt][1], ah[mt][2], ah[mt][3], ra);
                LDSM4(al[mt][0], al[mt][1], al[mt][2], al[mt][3], ra + TILE_B);
            }
            uint32_t bh[8][2], bl[8][2];
#pragma unroll
            for (int p = 0; p < 4; p++) {
                const uint32_t rb = sb + 2 * TILE_B +
                    (uint32_t)((wn + p * 16 + lrow) * LDS_W + kk + lcolsel) * 2;
                uint32_t r0, r1, r2, r3;
                LDSM4(r0, r1, r2, r3, rb);
                bh[2 * p][0] = r0; bh[2 * p + 1][0] = r1;
                bh[2 * p][1] = r2; bh[2 * p + 1][1] = r3;
                LDSM4(r0, r1, r2, r3, rb + TILE_B);
                bl[2 * p][0] = r0; bl[2 * p + 1][0] = r1;
                bl[2 * p][1] = r2; bl[2 * p + 1][1] = r3;
            }
#pragma unroll
            for (int mt = 0; mt < 2; mt++)
#pragma unroll
                for (int nt = 0; nt < 8; nt++) {
                    mma16816(acc[mt][nt], ah[mt], bh[nt]);
                    mma16816(acc[mt][nt], ah[mt], bl[nt]);
                    mma16816(acc[mt][nt], al[mt], bh[nt]);
                }
        }
        __syncthreads();
    }

    const int g = lane >> 2, t = lane & 3;
#pragma unroll
    for (int mt = 0; mt < 2; mt++) {
        const int r0 = bm + wm + mt * 16 + g;
#pragma unroll
        for (int nt = 0; nt < 8; nt++) {
            const int col = bn + wn + nt * 8 + 2 * t;
            *(float2*)&C[(size_t)r0 * HIDDEN + col] = make_float2(acc[mt][nt][0], acc[mt][nt][1]);
            *(float2*)&C[(size_t)(r0 + 8) * HIDDEN + col] = make_float2(acc[mt][nt][2], acc[mt][nt][3]);
        }
    }
}

// ---------------------------------------------------------------------------
// RoPE + split to bf16 hi/lo for Q and K.
// ---------------------------------------------------------------------------
__global__ void rope_split_kernel(const float* __restrict__ q, const float* __restrict__ k,
                                  __nv_bfloat16* __restrict__ qh, __nv_bfloat16* __restrict__ ql,
                                  __nv_bfloat16* __restrict__ kh, __nv_bfloat16* __restrict__ kl)
{
    int idx = blockIdx.x * blockDim.x + threadIdx.x;
    int d = idx & 63;
    int m = idx >> 10;
    int l = m & (SEQL - 1);
    int h = (idx >> 6) & (HEADS - 1);

    float e = (2.0f * (float)d) / 128.0f;
    float inv = 1.0f / powf(10000.0f, e);
    float ang = (float)l * inv;
    float s, c;
    sincosf(ang, &s, &c);

    size_t base = (size_t)m * HIDDEN + h * HD + d;
    float q1 = q[base], q2 = q[base + 64];
    float k1 = k[base], k2 = k[base + 64];
    float qa = q1 * c - q2 * s;
    float qb = q2 * c + q1 * s;
    float ka = k1 * c - k2 * s;
    float kb = k2 * c + k1 * s;

    __nv_bfloat16 t0;
    t0 = __float2bfloat16(qa); qh[base] = t0;      ql[base] = __float2bfloat16(qa - __bfloat162float(t0));
    t0 = __float2bfloat16(qb); qh[base + 64] = t0; ql[base + 64] = __float2bfloat16(qb - __bfloat162float(t0));
    t0 = __float2bfloat16(ka); kh[base] = t0;      kl[base] = __float2bfloat16(ka - __bfloat162float(t0));
    t0 = __float2bfloat16(kb); kh[base + 64] = t0; kl[base + 64] = __float2bfloat16(kb - __bfloat162float(t0));
}

// ---------------------------------------------------------------------------
// V transpose + split
// ---------------------------------------------------------------------------
__global__ __launch_bounds__(256) void vt_split_kernel(
    const float* __restrict__ v,
    __nv_bfloat16* __restrict__ vth, __nv_bfloat16* __restrict__ vtl)
{
    __shared__ float tile[32][33];
    const int bh = blockIdx.z;
    const int b = bh >> 4, h = bh & 15;
    const int l0 = blockIdx.x * 32, d0 = blockIdx.y * 32;
    const int tx = threadIdx.x, ty = threadIdx.y;

#pragma unroll
    for (int i = 0; i < 4; i++) {
        int r = ty + i * 8;
        tile[r][tx] = v[(size_t)(b * SEQL + l0 + r) * HIDDEN + h * HD + d0 + tx];
    }
    __syncthreads();
#pragma unroll
    for (int i = 0; i < 4; i++) {
        int r = ty + i * 8;
        float f = tile[tx][r];
        __nv_bfloat16 hi = __float2bfloat16(f);
        size_t o = ((size_t)((b * HEADS + h) * HD + d0 + r)) * SEQL + l0 + tx;
        vth[o] = hi;
        vtl[o] = __float2bfloat16(f - __bfloat162float(hi));
    }
}

// ---------------------------------------------------------------------------
// Flash attention on tensor cores (validated R4)
// ---------------------------------------------------------------------------
#define QW 136
#define VW 72
#define OQH 0
#define OQL 17408
#define OKH 34816
#define OKL 43520
#define OVH 52224
#define OVL 61440
#define FLASH_SMEM (70656 * 2)

__device__ __forceinline__ void pack_pair(float a, float b, uint32_t& hi_pack, uint32_t& lo_pack)
{
    uint32_t ph;
    asm("cvt.rn.bf16x2.f32 %0, %1, %2;" : "=r"(ph) : "f"(b), "f"(a));
    float ra = a - __uint_as_float(ph << 16);
    float rb = b - __uint_as_float(ph & 0xffff0000u);
    asm("cvt.rn.bf16x2.f32 %0, %1, %2;" : "=r"(lo_pack) : "f"(rb), "f"(ra));
    hi_pack = ph;
}

__global__ __launch_bounds__(256) void flash_mma_kernel(
    const __nv_bfloat16* __restrict__ Qh, const __nv_bfloat16* __restrict__ Ql,
    const __nv_bfloat16* __restrict__ Kh, const __nv_bfloat16* __restrict__ Kl,
    const __nv_bfloat16* __restrict__ Vth, const __nv_bfloat16* __restrict__ Vtl,
    float* __restrict__ O)
{
    extern __shared__ __nv_bfloat16 fs[];
    __nv_bfloat16* sQh = fs + OQH;
    __nv_bfloat16* sQl = fs + OQL;
    __nv_bfloat16* sKh = fs + OKH;
    __nv_bfloat16* sKl = fs + OKL;
    __nv_bfloat16* sVh = fs + OVH;
    __nv_bfloat16* sVl = fs + OVL;

    const int qt = blockIdx.x, h = blockIdx.y, b = blockIdx.z;
    const int tid = threadIdx.x, lane = tid & 31, wid = tid >> 5;
    const int g = lane >> 2, t = lane & 3;
    const int wm = wid * 16;
    const float scale = 0.0883883476483184f;

    {
        const size_t base = (size_t)(b * SEQL + qt * 128) * HIDDEN + h * HD;
#pragma unroll
        for (int it = 0; it < 8; it++) {
            int id = tid + it * 256;
            int r = id >> 4, c8 = (id & 15) * 8;
            *(uint4*)&sQh[r * QW + c8] = *(const uint4*)&Qh[base + (size_t)r * HIDDEN + c8];
            *(uint4*)&sQl[r * QW + c8] = *(const uint4*)&Ql[base + (size_t)r * HIDDEN + c8];
        }
    }

    float m0 = -1e30f, m1 = -1e30f, l0 = 0.f, l1 = 0.f;
    float oacc[16][4];
#pragma unroll
    for (int nt = 0; nt < 16; nt++)
#pragma unroll
        for (int r = 0; r < 4; r++) oacc[nt][r] = 0.f;

    const int nkt = 2 * qt + 2;
    for (int kt = 0; kt < nkt; kt++) {
        __syncthreads();
#pragma unroll
        for (int it = 0; it < 4; it++) {
            int id = tid + it * 256;
            int r = id >> 4, c8 = (id & 15) * 8;
            size_t gk = (size_t)(b * SEQL + kt * 64 + r) * HIDDEN + h * HD + c8;
            *(uint4*)&sKh[r * QW + c8] = *(const uint4*)&Kh[gk];
            *(uint4*)&sKl[r * QW + c8] = *(const uint4*)&Kl[gk];
            int rv = id >> 3, cv = (id & 7) * 8;
            size_t gv = (size_t)((b * HEADS + h) * HD + rv) * SEQL + kt * 64 + cv;
            *(uint4*)&sVh[rv * VW + cv] = *(const uint4*)&Vth[gv];
            *(uint4*)&sVl[rv * VW + cv] = *(const uint4*)&Vtl[gv];
        }
        __syncthreads();

        float sacc[8][4];
#pragma unroll
        for (int nt = 0; nt < 8; nt++)
#pragma unroll
            for (int r = 0; r < 4; r++) sacc[nt][r] = 0.f;

#pragma unroll
        for (int kc = 0; kc < 8; kc++) {
            const int kk = kc * 16;
            uint32_t aqh[4], aql[4];
            const __nv_bfloat16* ah = &sQh[(wm + g) * QW + kk + 2 * t];
            aqh[0] = *(const uint32_t*)ah;
            aqh[1] = *(const uint32_t*)(ah + 8 * QW);
            aqh[2] = *(const uint32_t*)(ah + 8);
            aqh[3] = *(const uint32_t*)(ah + 8 * QW + 8);
            const __nv_bfloat16* al = &sQl[(wm + g) * QW + kk + 2 * t];
            aql[0] = *(const uint32_t*)al;
            aql[1] = *(const uint32_t*)(al + 8 * QW);
            aql[2] = *(const uint32_t*)(al + 8);
            aql[3] = *(const uint32_t*)(al + 8 * QW + 8);
#pragma unroll
            for (int nt = 0; nt < 8; nt++) {
                const __nv_bfloat16* bh = &sKh[(nt * 8 + g) * QW + kk + 2 * t];
                uint32_t bhf[2] = { *(const uint32_t*)bh, *(const uint32_t*)(bh + 8) };
                const __nv_bfloat16* bl = &sKl[(nt * 8 + g) * QW + kk + 2 * t];
                uint32_t blf[2] = { *(const uint32_t*)bl, *(const uint32_t*)(bl + 8) };
                mma16816(sacc[nt], aqh, bhf);
                mma16816(sacc[nt], aqh, blf);
                mma16816(sacc[nt], aql, bhf);
            }
        }

        const int row0 = qt * 128 + wm + g;
        const int row1 = row0 + 8;
#pragma unroll
        for (int nt = 0; nt < 8; nt++) {
            sacc[nt][0] *= scale; sacc[nt][1] *= scale;
            sacc[nt][2] *= scale; sacc[nt][3] *= scale;
        }
        if (kt * 64 + 63 > qt * 128 + wm) {
#pragma unroll
            for (int nt = 0; nt < 8; nt++) {
                const int col = kt * 64 + nt * 8 + 2 * t;
                if (col > row0)     sacc[nt][0] = -1e30f;
                if (col + 1 > row0) sacc[nt][1] = -1e30f;
                if (col > row1)     sacc[nt][2] = -1e30f;
                if (col + 1 > row1) sacc[nt][3] = -1e30f;
            }
        }

        float mt0 = -1e30f, mt1 = -1e30f;
#pragma unroll
        for (int nt = 0; nt < 8; nt++) {
            mt0 = fmaxf(mt0, fmaxf(sacc[nt][0], sacc[nt][1]));
            mt1 = fmaxf(mt1, fmaxf(sacc[nt][2], sacc[nt][3]));
        }
        mt0 = fmaxf(mt0, __shfl_xor_sync(0xffffffffu, mt0, 1));
        mt0 = fmaxf(mt0, __shfl_xor_sync(0xffffffffu, mt0, 2));
        mt1 = fmaxf(mt1, __shfl_xor_sync(0xffffffffu, mt1, 1));
        mt1 = fmaxf(mt1, __shfl_xor_sync(0xffffffffu, mt1, 2));

        const float nm0 = fmaxf(m0, mt0), nm1 = fmaxf(m1, mt1);
        const float alpha0 = __expf(m0 - nm0), alpha1 = __expf(m1 - nm1);
        float ps0 = 0.f, ps1 = 0.f;
#pragma unroll
        for (int nt = 0; nt < 8; nt++) {
            sacc[nt][0] = __expf(sacc[nt][0] - nm0);
            sacc[nt][1] = __expf(sacc[nt][1] - nm0);
            sacc[nt][2] = __expf(sacc[nt][2] - nm1);
            sacc[nt][3] = __expf(sacc[nt][3] - nm1);
            ps0 += sacc[nt][0] + sacc[nt][1];
            ps1 += sacc[nt][2] + sacc[nt][3];
        }
        ps0 += __shfl_xor_sync(0xffffffffu, ps0, 1);
        ps0 += __shfl_xor_sync(0xffffffffu, ps0, 2);
        ps1 += __shfl_xor_sync(0xffffffffu, ps1, 1);
        ps1 += __shfl_xor_sync(0xffffffffu, ps1, 2);
        l0 = alpha0 * l0 + ps0; m0 = nm0;
        l1 = alpha1 * l1 + ps1; m1 = nm1;
#pragma unroll
        for (int nt = 0; nt < 16; nt++) {
            oacc[nt][0] *= alpha0; oacc[nt][1] *= alpha0;
            oacc[nt][2] *= alpha1; oacc[nt][3] *= alpha1;
        }

        uint32_t ph[4][4], pl[4][4];
#pragma unroll
        for (int kc = 0; kc < 4; kc++) {
            const int j0 = 2 * kc, j1 = 2 * kc + 1;
            pack_pair(sacc[j0][0], sacc[j0][1], ph[kc][0], pl[kc][0]);
            pack_pair(sacc[j0][2], sacc[j0][3], ph[kc][1], pl[kc][1]);
            pack_pair(sacc[j1][0], sacc[j1][1], ph[kc][2], pl[kc][2]);
            pack_pair(sacc[j1][2], sacc[j1][3], ph[kc][3], pl[kc][3]);
        }

#pragma unroll
        for (int kc = 0; kc < 4; kc++) {
#pragma unroll
            for (int nt = 0; nt < 16; nt++) {
                const __nv_bfloat16* vh = &sVh[(nt * 8 + g) * VW + kc * 16 + 2 * t];
                uint32_t bvh[2] = { *(const uint32_t*)vh, *(const uint32_t*)(vh + 8) };
                const __nv_bfloat16* vl = &sVl[(nt * 8 + g) * VW + kc * 16 + 2 * t];
                uint32_t bvl[2] = { *(const uint32_t*)vl, *(const uint32_t*)(vl + 8) };
                mma16816(oacc[nt], ph[kc], bvh);
                mma16816(oacc[nt], ph[kc], bvl);
                mma16816(oacc[nt], pl[kc], bvh);
            }
        }
    }

    const float i0 = 1.0f / l0, i1 = 1.0f / l1;
    const size_t rbase = (size_t)(b * SEQL + qt * 128 + wm + g) * HIDDEN + h * HD + 2 * t;
#pragma unroll
    for (int nt = 0; nt < 16; nt++) {
        *(float2*)&O[rbase + nt * 8] = make_float2(oacc[nt][0] * i0, oacc[nt][1] * i0);
        *(float2*)&O[rbase + 8 * HIDDEN + nt * 8] = make_float2(oacc[nt][2] * i1, oacc[nt][3] * i1);
    }
}

// ---------------------------------------------------------------------------
extern "C" void kernel_launch(void* const* d_in, const int* in_sizes, int n_in,
                              void* d_out, int out_size)
{
    const float* x  = (const float*)d_in[0];
    const float* wq = (const float*)d_in[1];
    const float* wk = (const float*)d_in[2];
    const float* wv = (const float*)d_in[3];
    const float* wo = (const float*)d_in[4];
    float* out = (float*)d_out;

    float *q, *k, *v, *o;
    cudaGetSymbolAddress((void**)&q, g_q);
    cudaGetSymbolAddress((void**)&k, g_k);
    cudaGetSymbolAddress((void**)&v, g_v);
    cudaGetSymbolAddress((void**)&o, g_o);

    __nv_bfloat16 *xh, *xl, *oh, *ol;
    __nv_bfloat16 *wqh, *wql, *wkh, *wkl, *wvh, *wvl, *woh, *wol;
    __nv_bfloat16 *qh, *ql, *kh, *kl, *vth, *vtl;
    cudaGetSymbolAddress((void**)&xh, g_xh);
    cudaGetSymbolAddress((void**)&xl, g_xl);
    cudaGetSymbolAddress((void**)&oh, g_oh);
    cudaGetSymbolAddress((void**)&ol, g_ol);
    cudaGetSymbolAddress((void**)&wqh, g_wqh);
    cudaGetSymbolAddress((void**)&wql, g_wql);
    cudaGetSymbolAddress((void**)&wkh, g_wkh);
    cudaGetSymbolAddress((void**)&wkl, g_wkl);
    cudaGetSymbolAddress((void**)&wvh, g_wvh);
    cudaGetSymbolAddress((void**)&wvl, g_wvl);
    cudaGetSymbolAddress((void**)&woh, g_woh);
    cudaGetSymbolAddress((void**)&wol, g_wol);
    cudaGetSymbolAddress((void**)&qh, g_qh);
    cudaGetSymbolAddress((void**)&ql, g_ql);
    cudaGetSymbolAddress((void**)&kh, g_kh);
    cudaGetSymbolAddress((void**)&kl, g_kl);
    cudaGetSymbolAddress((void**)&vth, g_vth);
    cudaGetSymbolAddress((void**)&vtl, g_vtl);

    const int nx4 = MROWS * HIDDEN / 4;
    const int nw4 = HIDDEN * HIDDEN / 4;
    split_kernel<<<(nx4 + 255) / 256, 256>>>((const float4*)x, xh, xl, nx4);
    split_kernel<<<(nw4 + 255) / 256, 256>>>((const float4*)wq, wqh, wql, nw4);
    split_kernel<<<(nw4 + 255) / 256, 256>>>((const float4*)wk, wkh, wkl, nw4);
    split_kernel<<<(nw4 + 255) / 256, 256>>>((const float4*)wv, wvh, wvl, nw4);
    split_kernel<<<(nw4 + 255) / 256, 256>>>((const float4*)wo, woh, wol, nw4);

    const int gemm_smem = NSTAGE * STAGE_B; // 122880
    cudaFuncSetAttribute(gemm3_kernel, cudaFuncAttributeMaxDynamicSharedMemorySize, gemm_smem);
    dim3 gg(HIDDEN / GBN, MROWS / GBM); // (16, 32)
    gemm3_kernel<<<gg, 256, gemm_smem>>>(xh, xl, wqh, wql, q);
    gemm3_kernel<<<gg, 256, gemm_smem>>>(xh, xl, wkh, wkl, k);
    gemm3_kernel<<<gg, 256, gemm_smem>>>(xh, xl, wvh, wvl, v);

    rope_split_kernel<<<(MROWS * HEADS * 64) / 256, 256>>>(q, k, qh, ql, kh, kl);
    vt_split_kernel<<<dim3(SEQL / 32, HD / 32, NBATCH * HEADS), dim3(32, 8)>>>(v, vth, vtl);

    cudaFuncSetAttribute(flash_mma_kernel, cudaFuncAttributeMaxDynamicSharedMemorySize, FLASH_SMEM);
    flash_mma_kernel<<<dim3(SEQL / 128, HEADS, NBATCH), 256, FLASH_SMEM>>>(
        qh, ql, kh, kl, vth, vtl, o);

    split_kernel<<<(nx4 + 255) / 256, 256>>>((const float4*)o, oh, ol, nx4);
    gemm3_kernel<<<gg, 256, gemm_smem>>>(oh, ol, woh, wol, out);
}

// round 10
// speedup vs baseline: 1.3661x; 1.3661x over previous
#include <cuda_runtime.h>
#include <cuda_bf16.h>
#include <math.h>
#include <stdint.h>

#define HIDDEN 2048
#define HEADS 16
#define HD 128
#define SEQL 2048
#define NBATCH 2
#define MROWS (NBATCH * SEQL) // 4096
#define KDIM 2048

// ---------------------------------------------------------------------------
// Scratch: __device__ globals (no cudaMalloc allowed)
// ---------------------------------------------------------------------------
__device__ float g_q[(size_t)MROWS * HIDDEN];
__device__ float g_k[(size_t)MROWS * HIDDEN];
__device__ float g_v[(size_t)MROWS * HIDDEN];
__device__ float g_o[(size_t)MROWS * HIDDEN];

__device__ __nv_bfloat16 g_xh[(size_t)MROWS * HIDDEN];
__device__ __nv_bfloat16 g_xl[(size_t)MROWS * HIDDEN];
__device__ __nv_bfloat16 g_oh[(size_t)MROWS * HIDDEN];
__device__ __nv_bfloat16 g_ol[(size_t)MROWS * HIDDEN];
__device__ __nv_bfloat16 g_wqh[(size_t)HIDDEN * HIDDEN];
__device__ __nv_bfloat16 g_wql[(size_t)HIDDEN * HIDDEN];
__device__ __nv_bfloat16 g_wkh[(size_t)HIDDEN * HIDDEN];
__device__ __nv_bfloat16 g_wkl[(size_t)HIDDEN * HIDDEN];
__device__ __nv_bfloat16 g_wvh[(size_t)HIDDEN * HIDDEN];
__device__ __nv_bfloat16 g_wvl[(size_t)HIDDEN * HIDDEN];
__device__ __nv_bfloat16 g_woh[(size_t)HIDDEN * HIDDEN];
__device__ __nv_bfloat16 g_wol[(size_t)HIDDEN * HIDDEN];

// bf16 split Q/K (post-RoPE) and transposed V for flash
__device__ __nv_bfloat16 g_qh[(size_t)MROWS * HIDDEN];
__device__ __nv_bfloat16 g_ql[(size_t)MROWS * HIDDEN];
__device__ __nv_bfloat16 g_kh[(size_t)MROWS * HIDDEN];
__device__ __nv_bfloat16 g_kl[(size_t)MROWS * HIDDEN];
__device__ __nv_bfloat16 g_vth[(size_t)MROWS * HIDDEN];
__device__ __nv_bfloat16 g_vtl[(size_t)MROWS * HIDDEN];

// ---------------------------------------------------------------------------
__device__ __forceinline__ void mma16816(float* c, const uint32_t* a, const uint32_t* b)
{
    asm volatile(
        "mma.sync.aligned.m16n8k16.row.col.f32.bf16.bf16.f32 "
        "{%0,%1,%2,%3}, {%4,%5,%6,%7}, {%8,%9}, {%0,%1,%2,%3};"
        : "+f"(c[0]), "+f"(c[1]), "+f"(c[2]), "+f"(c[3])
        : "r"(a[0]), "r"(a[1]), "r"(a[2]), "r"(a[3]), "r"(b[0]), "r"(b[1]));
}

#define LDSM4(r0, r1, r2, r3, addr) \
    asm volatile("ldmatrix.sync.aligned.m8n8.x4.shared.b16 {%0,%1,%2,%3}, [%4];" \
                 : "=r"(r0), "=r"(r1), "=r"(r2), "=r"(r3) : "r"(addr))

// ---------------------------------------------------------------------------
// Split fp32 -> (bf16 hi, bf16 lo) elementwise, vectorized x4
// ---------------------------------------------------------------------------
__global__ void split_kernel(const float4* __restrict__ a,
                             __nv_bfloat16* __restrict__ hi,
                             __nv_bfloat16* __restrict__ lo, int n4)
{
    int i = blockIdx.x * blockDim.x + threadIdx.x;
    if (i >= n4) return;
    float4 v = a[i];
    __nv_bfloat16 h0 = __float2bfloat16(v.x);
    __nv_bfloat16 h1 = __float2bfloat16(v.y);
    __nv_bfloat16 h2 = __float2bfloat16(v.z);
    __nv_bfloat16 h3 = __float2bfloat16(v.w);
    __nv_bfloat16 l0 = __float2bfloat16(v.x - __bfloat162float(h0));
    __nv_bfloat16 l1 = __float2bfloat16(v.y - __bfloat162float(h1));
    __nv_bfloat16 l2 = __float2bfloat16(v.z - __bfloat162float(h2));
    __nv_bfloat16 l3 = __float2bfloat16(v.w - __bfloat162float(h3));
    ushort4 hv, lv;
    hv.x = __bfloat16_as_ushort(h0); hv.y = __bfloat16_as_ushort(h1);
    hv.z = __bfloat16_as_ushort(h2); hv.w = __bfloat16_as_ushort(h3);
    lv.x = __bfloat16_as_ushort(l0); lv.y = __bfloat16_as_ushort(l1);
    lv.z = __bfloat16_as_ushort(l2); lv.w = __bfloat16_as_ushort(l3);
    *(ushort4*)(hi + (size_t)i * 4) = hv;
    *(ushort4*)(lo + (size_t)i * 4) = lv;
}

// ---------------------------------------------------------------------------
// bf16x3 GEMM via mma.sync.m16n8k16, R4 skeleton (register double buffer,
// 3 K-passes, 40KB static smem, 2 CTA/SM) + ldmatrix.x4 fragment loads.
// ---------------------------------------------------------------------------
#define GBM 128
#define GBN 128
#define GBK 32
#define LDS_W 40
#define TILE_B2 (GBM * LDS_W * 2)   // bytes per buffer = 10240
#define NCHUNK (3 * KDIM / GBK)     // 192

__global__ __launch_bounds__(256) void gemm3_kernel(
    const __nv_bfloat16* __restrict__ Ah, const __nv_bfloat16* __restrict__ Al,
    const __nv_bfloat16* __restrict__ Bh, const __nv_bfloat16* __restrict__ Bl,
    float* __restrict__ C)
{
    __shared__ __nv_bfloat16 sA[2][GBM * LDS_W];
    __shared__ __nv_bfloat16 sB[2][GBN * LDS_W];

    const int tid = threadIdx.x;
    const int lane = tid & 31;
    const int wid = tid >> 5;
    const int wm = (wid & 3) * 32;
    const int wn = (wid >> 2) * 64;
    const int g = lane >> 2;
    const int t = lane & 3;
    const int lrow = lane & 15;          // ldmatrix source row
    const int lsel = (lane >> 4) * 8;    // ldmatrix col half

    const int bm = blockIdx.y * GBM;
    const int bn = blockIdx.x * GBN;

    const int grow = tid >> 1;
    const int gcol = (tid & 1) * 16;

    const uint32_t sAu = (uint32_t)__cvta_generic_to_shared(&sA[0][0]);
    const uint32_t sBu = (uint32_t)__cvta_generic_to_shared(&sB[0][0]);

    float acc[2][8][4];
#pragma unroll
    for (int i = 0; i < 2; i++)
#pragma unroll
        for (int j = 0; j < 8; j++)
#pragma unroll
            for (int r = 0; r < 4; r++) acc[i][j][r] = 0.f;

    auto fetch = [&](int c, uint4& ra0, uint4& ra1, uint4& rb0, uint4& rb1) {
        const int pass = c >> 6;
        const int k0 = (c & 63) * GBK;
        const __nv_bfloat16* Ap = (pass == 2) ? Al : Ah;
        const __nv_bfloat16* Bp = (pass == 1) ? Bl : Bh;
        const size_t ga = (size_t)(bm + grow) * KDIM + k0 + gcol;
        const size_t gb = (size_t)(bn + grow) * KDIM + k0 + gcol;
        ra0 = *(const uint4*)(Ap + ga);
        ra1 = *(const uint4*)(Ap + ga + 8);
        rb0 = *(const uint4*)(Bp + gb);
        rb1 = *(const uint4*)(Bp + gb + 8);
    };
    auto store = [&](int buf, const uint4& ra0, const uint4& ra1,
                     const uint4& rb0, const uint4& rb1) {
        __nv_bfloat16* pa = &sA[buf][grow * LDS_W + gcol];
        __nv_bfloat16* pb = &sB[buf][grow * LDS_W + gcol];
        *(uint4*)pa = ra0;
        *(uint4*)(pa + 8) = ra1;
        *(uint4*)pb = rb0;
        *(uint4*)(pb + 8) = rb1;
    };

    {
        uint4 ra0, ra1, rb0, rb1;
        fetch(0, ra0, ra1, rb0, rb1);
        store(0, ra0, ra1, rb0, rb1);
    }
    __syncthreads();

    for (int c = 0; c < NCHUNK; c++) {
        const int buf = c & 1;
        const bool more = (c + 1 < NCHUNK);
        uint4 ra0, ra1, rb0, rb1;
        if (more) fetch(c + 1, ra0, ra1, rb0, rb1);

        const uint32_t sa = sAu + (uint32_t)buf * TILE_B2;
        const uint32_t sb = sBu + (uint32_t)buf * TILE_B2;
#pragma unroll
        for (int kk = 0; kk < GBK; kk += 16) {
            uint32_t af[2][4];
#pragma unroll
            for (int mt = 0; mt < 2; mt++) {
                const uint32_t ra = sa + (uint32_t)((wm + mt * 16 + lrow) * LDS_W + kk + lsel) * 2;
                LDSM4(af[mt][0], af[mt][1], af[mt][2], af[mt][3], ra);
            }
            uint32_t bfr[8][2];
#pragma unroll
            for (int p = 0; p < 4; p++) {
                const uint32_t rb = sb + (uint32_t)((wn + p * 16 + lrow) * LDS_W + kk + lsel) * 2;
                uint32_t r0, r1, r2, r3;
                LDSM4(r0, r1, r2, r3, rb);
                bfr[2 * p][0] = r0; bfr[2 * p + 1][0] = r1;
                bfr[2 * p][1] = r2; bfr[2 * p + 1][1] = r3;
            }
#pragma unroll
            for (int mt = 0; mt < 2; mt++)
#pragma unroll
                for (int nt = 0; nt < 8; nt++)
                    mma16816(acc[mt][nt], af[mt], bfr[nt]);
        }

        if (more) store(buf ^ 1, ra0, ra1, rb0, rb1);
        __syncthreads();
    }

#pragma unroll
    for (int mt = 0; mt < 2; mt++) {
        const int r0 = bm + wm + mt * 16 + g;
#pragma unroll
        for (int nt = 0; nt < 8; nt++) {
            const int col = bn + wn + nt * 8 + 2 * t;
            *(float2*)&C[(size_t)r0 * HIDDEN + col] = make_float2(acc[mt][nt][0], acc[mt][nt][1]);
            *(float2*)&C[(size_t)(r0 + 8) * HIDDEN + col] = make_float2(acc[mt][nt][2], acc[mt][nt][3]);
        }
    }
}

// ---------------------------------------------------------------------------
// RoPE + split to bf16 hi/lo for Q and K.
// ---------------------------------------------------------------------------
__global__ void rope_split_kernel(const float* __restrict__ q, const float* __restrict__ k,
                                  __nv_bfloat16* __restrict__ qh, __nv_bfloat16* __restrict__ ql,
                                  __nv_bfloat16* __restrict__ kh, __nv_bfloat16* __restrict__ kl)
{
    int idx = blockIdx.x * blockDim.x + threadIdx.x;
    int d = idx & 63;
    int m = idx >> 10;
    int l = m & (SEQL - 1);
    int h = (idx >> 6) & (HEADS - 1);

    float e = (2.0f * (float)d) / 128.0f;
    float inv = 1.0f / powf(10000.0f, e);
    float ang = (float)l * inv;
    float s, c;
    sincosf(ang, &s, &c);

    size_t base = (size_t)m * HIDDEN + h * HD + d;
    float q1 = q[base], q2 = q[base + 64];
    float k1 = k[base], k2 = k[base + 64];
    float qa = q1 * c - q2 * s;
    float qb = q2 * c + q1 * s;
    float ka = k1 * c - k2 * s;
    float kb = k2 * c + k1 * s;

    __nv_bfloat16 t0;
    t0 = __float2bfloat16(qa); qh[base] = t0;      ql[base] = __float2bfloat16(qa - __bfloat162float(t0));
    t0 = __float2bfloat16(qb); qh[base + 64] = t0; ql[base + 64] = __float2bfloat16(qb - __bfloat162float(t0));
    t0 = __float2bfloat16(ka); kh[base] = t0;      kl[base] = __float2bfloat16(ka - __bfloat162float(t0));
    t0 = __float2bfloat16(kb); kh[base + 64] = t0; kl[base + 64] = __float2bfloat16(kb - __bfloat162float(t0));
}

// ---------------------------------------------------------------------------
// V transpose + split
// ---------------------------------------------------------------------------
__global__ __launch_bounds__(256) void vt_split_kernel(
    const float* __restrict__ v,
    __nv_bfloat16* __restrict__ vth, __nv_bfloat16* __restrict__ vtl)
{
    __shared__ float tile[32][33];
    const int bh = blockIdx.z;
    const int b = bh >> 4, h = bh & 15;
    const int l0 = blockIdx.x * 32, d0 = blockIdx.y * 32;
    const int tx = threadIdx.x, ty = threadIdx.y;

#pragma unroll
    for (int i = 0; i < 4; i++) {
        int r = ty + i * 8;
        tile[r][tx] = v[(size_t)(b * SEQL + l0 + r) * HIDDEN + h * HD + d0 + tx];
    }
    __syncthreads();
#pragma unroll
    for (int i = 0; i < 4; i++) {
        int r = ty + i * 8;
        float f = tile[tx][r];
        __nv_bfloat16 hi = __float2bfloat16(f);
        size_t o = ((size_t)((b * HEADS + h) * HD + d0 + r)) * SEQL + l0 + tx;
        vth[o] = hi;
        vtl[o] = __float2bfloat16(f - __bfloat162float(hi));
    }
}

// ---------------------------------------------------------------------------
// Flash attention on tensor cores (validated R4)
// ---------------------------------------------------------------------------
#define QW 136
#define VW 72
#define OQH 0
#define OQL 17408
#define OKH 34816
#define OKL 43520
#define OVH 52224
#define OVL 61440
#define FLASH_SMEM (70656 * 2)

__device__ __forceinline__ void pack_pair(float a, float b, uint32_t& hi_pack, uint32_t& lo_pack)
{
    uint32_t ph;
    asm("cvt.rn.bf16x2.f32 %0, %1, %2;" : "=r"(ph) : "f"(b), "f"(a));
    float ra = a - __uint_as_float(ph << 16);
    float rb = b - __uint_as_float(ph & 0xffff0000u);
    asm("cvt.rn.bf16x2.f32 %0, %1, %2;" : "=r"(lo_pack) : "f"(rb), "f"(ra));
    hi_pack = ph;
}

__global__ __launch_bounds__(256) void flash_mma_kernel(
    const __nv_bfloat16* __restrict__ Qh, const __nv_bfloat16* __restrict__ Ql,
    const __nv_bfloat16* __restrict__ Kh, const __nv_bfloat16* __restrict__ Kl,
    const __nv_bfloat16* __restrict__ Vth, const __nv_bfloat16* __restrict__ Vtl,
    float* __restrict__ O)
{
    extern __shared__ __nv_bfloat16 fs[];
    __nv_bfloat16* sQh = fs + OQH;
    __nv_bfloat16* sQl = fs + OQL;
    __nv_bfloat16* sKh = fs + OKH;
    __nv_bfloat16* sKl = fs + OKL;
    __nv_bfloat16* sVh = fs + OVH;
    __nv_bfloat16* sVl = fs + OVL;

    const int qt = blockIdx.x, h = blockIdx.y, b = blockIdx.z;
    const int tid = threadIdx.x, lane = tid & 31, wid = tid >> 5;
    const int g = lane >> 2, t = lane & 3;
    const int wm = wid * 16;
    const float scale = 0.0883883476483184f;

    {
        const size_t base = (size_t)(b * SEQL + qt * 128) * HIDDEN + h * HD;
#pragma unroll
        for (int it = 0; it < 8; it++) {
            int id = tid + it * 256;
            int r = id >> 4, c8 = (id & 15) * 8;
            *(uint4*)&sQh[r * QW + c8] = *(const uint4*)&Qh[base + (size_t)r * HIDDEN + c8];
            *(uint4*)&sQl[r * QW + c8] = *(const uint4*)&Ql[base + (size_t)r * HIDDEN + c8];
        }
    }

    float m0 = -1e30f, m1 = -1e30f, l0 = 0.f, l1 = 0.f;
    float oacc[16][4];
#pragma unroll
    for (int nt = 0; nt < 16; nt++)
#pragma unroll
        for (int r = 0; r < 4; r++) oacc[nt][r] = 0.f;

    const int nkt = 2 * qt + 2;
    for (int kt = 0; kt < nkt; kt++) {
        __syncthreads();
#pragma unroll
        for (int it = 0; it < 4; it++) {
            int id = tid + it * 256;
            int r = id >> 4, c8 = (id & 15) * 8;
            size_t gk = (size_t)(b * SEQL + kt * 64 + r) * HIDDEN + h * HD + c8;
            *(uint4*)&sKh[r * QW + c8] = *(const uint4*)&Kh[gk];
            *(uint4*)&sKl[r * QW + c8] = *(const uint4*)&Kl[gk];
            int rv = id >> 3, cv = (id & 7) * 8;
            size_t gv = (size_t)((b * HEADS + h) * HD + rv) * SEQL + kt * 64 + cv;
            *(uint4*)&sVh[rv * VW + cv] = *(const uint4*)&Vth[gv];
            *(uint4*)&sVl[rv * VW + cv] = *(const uint4*)&Vtl[gv];
        }
        __syncthreads();

        float sacc[8][4];
#pragma unroll
        for (int nt = 0; nt < 8; nt++)
#pragma unroll
            for (int r = 0; r < 4; r++) sacc[nt][r] = 0.f;

#pragma unroll
        for (int kc = 0; kc < 8; kc++) {
            const int kk = kc * 16;
            uint32_t aqh[4], aql[4];
            const __nv_bfloat16* ah = &sQh[(wm + g) * QW + kk + 2 * t];
            aqh[0] = *(const uint32_t*)ah;
            aqh[1] = *(const uint32_t*)(ah + 8 * QW);
            aqh[2] = *(const uint32_t*)(ah + 8);
            aqh[3] = *(const uint32_t*)(ah + 8 * QW + 8);
            const __nv_bfloat16* al = &sQl[(wm + g) * QW + kk + 2 * t];
            aql[0] = *(const uint32_t*)al;
            aql[1] = *(const uint32_t*)(al + 8 * QW);
            aql[2] = *(const uint32_t*)(al + 8);
            aql[3] = *(const uint32_t*)(al + 8 * QW + 8);
#pragma unroll
            for (int nt = 0; nt < 8; nt++) {
                const __nv_bfloat16* bh = &sKh[(nt * 8 + g) * QW + kk + 2 * t];
                uint32_t bhf[2] = { *(const uint32_t*)bh, *(const uint32_t*)(bh + 8) };
                const __nv_bfloat16* bl = &sKl[(nt * 8 + g) * QW + kk + 2 * t];
                uint32_t blf[2] = { *(const uint32_t*)bl, *(const uint32_t*)(bl + 8) };
                mma16816(sacc[nt], aqh, bhf);
                mma16816(sacc[nt], aqh, blf);
                mma16816(sacc[nt], aql, bhf);
            }
        }

        const int row0 = qt * 128 + wm + g;
        const int row1 = row0 + 8;
#pragma unroll
        for (int nt = 0; nt < 8; nt++) {
            sacc[nt][0] *= scale; sacc[nt][1] *= scale;
            sacc[nt][2] *= scale; sacc[nt][3] *= scale;
        }
        if (kt * 64 + 63 > qt * 128 + wm) {
#pragma unroll
            for (int nt = 0; nt < 8; nt++) {
                const int col = kt * 64 + nt * 8 + 2 * t;
                if (col > row0)     sacc[nt][0] = -1e30f;
                if (col + 1 > row0) sacc[nt][1] = -1e30f;
                if (col > row1)     sacc[nt][2] = -1e30f;
                if (col + 1 > row1) sacc[nt][3] = -1e30f;
            }
        }

        float mt0 = -1e30f, mt1 = -1e30f;
#pragma unroll
        for (int nt = 0; nt < 8; nt++) {
            mt0 = fmaxf(mt0, fmaxf(sacc[nt][0], sacc[nt][1]));
            mt1 = fmaxf(mt1, fmaxf(sacc[nt][2], sacc[nt][3]));
        }
        mt0 = fmaxf(mt0, __shfl_xor_sync(0xffffffffu, mt0, 1));
        mt0 = fmaxf(mt0, __shfl_xor_sync(0xffffffffu, mt0, 2));
        mt1 = fmaxf(mt1, __shfl_xor_sync(0xffffffffu, mt1, 1));
        mt1 = fmaxf(mt1, __shfl_xor_sync(0xffffffffu, mt1, 2));

        const float nm0 = fmaxf(m0, mt0), nm1 = fmaxf(m1, mt1);
        const float alpha0 = __expf(m0 - nm0), alpha1 = __expf(m1 - nm1);
        float ps0 = 0.f, ps1 = 0.f;
#pragma unroll
        for (int nt = 0; nt < 8; nt++) {
            sacc[nt][0] = __expf(sacc[nt][0] - nm0);
            sacc[nt][1] = __expf(sacc[nt][1] - nm0);
            sacc[nt][2] = __expf(sacc[nt][2] - nm1);
            sacc[nt][3] = __expf(sacc[nt][3] - nm1);
            ps0 += sacc[nt][0] + sacc[nt][1];
            ps1 += sacc[nt][2] + sacc[nt][3];
        }
        ps0 += __shfl_xor_sync(0xffffffffu, ps0, 1);
        ps0 += __shfl_xor_sync(0xffffffffu, ps0, 2);
        ps1 += __shfl_xor_sync(0xffffffffu, ps1, 1);
        ps1 += __shfl_xor_sync(0xffffffffu, ps1, 2);
        l0 = alpha0 * l0 + ps0; m0 = nm0;
        l1 = alpha1 * l1 + ps1; m1 = nm1;
#pragma unroll
        for (int nt = 0; nt < 16; nt++) {
            oacc[nt][0] *= alpha0; oacc[nt][1] *= alpha0;
            oacc[nt][2] *= alpha1; oacc[nt][3] *= alpha1;
        }

        uint32_t ph[4][4], pl[4][4];
#pragma unroll
        for (int kc = 0; kc < 4; kc++) {
            const int j0 = 2 * kc, j1 = 2 * kc + 1;
            pack_pair(sacc[j0][0], sacc[j0][1], ph[kc][0], pl[kc][0]);
            pack_pair(sacc[j0][2], sacc[j0][3], ph[kc][1], pl[kc][1]);
            pack_pair(sacc[j1][0], sacc[j1][1], ph[kc][2], pl[kc][2]);
            pack_pair(sacc[j1][2], sacc[j1][3], ph[kc][3], pl[kc][3]);
        }

#pragma unroll
        for (int kc = 0; kc < 4; kc++) {
#pragma unroll
            for (int nt = 0; nt < 16; nt++) {
                const __nv_bfloat16* vh = &sVh[(nt * 8 + g) * VW + kc * 16 + 2 * t];
                uint32_t bvh[2] = { *(const uint32_t*)vh, *(const uint32_t*)(vh + 8) };
                const __nv_bfloat16* vl = &sVl[(nt * 8 + g) * VW + kc * 16 + 2 * t];
                uint32_t bvl[2] = { *(const uint32_t*)vl, *(const uint32_t*)(vl + 8) };
                mma16816(oacc[nt], ph[kc], bvh);
                mma16816(oacc[nt], ph[kc], bvl);
                mma16816(oacc[nt], pl[kc], bvh);
            }
        }
    }

    const float i0 = 1.0f / l0, i1 = 1.0f / l1;
    const size_t rbase = (size_t)(b * SEQL + qt * 128 + wm + g) * HIDDEN + h * HD + 2 * t;
#pragma unroll
    for (int nt = 0; nt < 16; nt++) {
        *(float2*)&O[rbase + nt * 8] = make_float2(oacc[nt][0] * i0, oacc[nt][1] * i0);
        *(float2*)&O[rbase + 8 * HIDDEN + nt * 8] = make_float2(oacc[nt][2] * i1, oacc[nt][3] * i1);
    }
}

// ---------------------------------------------------------------------------
extern "C" void kernel_launch(void* const* d_in, const int* in_sizes, int n_in,
                              void* d_out, int out_size)
{
    const float* x  = (const float*)d_in[0];
    const float* wq = (const float*)d_in[1];
    const float* wk = (const float*)d_in[2];
    const float* wv = (const float*)d_in[3];
    const float* wo = (const float*)d_in[4];
    float* out = (float*)d_out;

    float *q, *k, *v, *o;
    cudaGetSymbolAddress((void**)&q, g_q);
    cudaGetSymbolAddress((void**)&k, g_k);
    cudaGetSymbolAddress((void**)&v, g_v);
    cudaGetSymbolAddress((void**)&o, g_o);

    __nv_bfloat16 *xh, *xl, *oh, *ol;
    __nv_bfloat16 *wqh, *wql, *wkh, *wkl, *wvh, *wvl, *woh, *wol;
    __nv_bfloat16 *qh, *ql, *kh, *kl, *vth, *vtl;
    cudaGetSymbolAddress((void**)&xh, g_xh);
    cudaGetSymbolAddress((void**)&xl, g_xl);
    cudaGetSymbolAddress((void**)&oh, g_oh);
    cudaGetSymbolAddress((void**)&ol, g_ol);
    cudaGetSymbolAddress((void**)&wqh, g_wqh);
    cudaGetSymbolAddress((void**)&wql, g_wql);
    cudaGetSymbolAddress((void**)&wkh, g_wkh);
    cudaGetSymbolAddress((void**)&wkl, g_wkl);
    cudaGetSymbolAddress((void**)&wvh, g_wvh);
    cudaGetSymbolAddress((void**)&wvl, g_wvl);
    cudaGetSymbolAddress((void**)&woh, g_woh);
    cudaGetSymbolAddress((void**)&wol, g_wol);
    cudaGetSymbolAddress((void**)&qh, g_qh);
    cudaGetSymbolAddress((void**)&ql, g_ql);
    cudaGetSymbolAddress((void**)&kh, g_kh);
    cudaGetSymbolAddress((void**)&kl, g_kl);
    cudaGetSymbolAddress((void**)&vth, g_vth);
    cudaGetSymbolAddress((void**)&vtl, g_vtl);

    const int nx4 = MROWS * HIDDEN / 4;
    const int nw4 = HIDDEN * HIDDEN / 4;
    split_kernel<<<(nx4 + 255) / 256, 256>>>((const float4*)x, xh, xl, nx4);
    split_kernel<<<(nw4 + 255) / 256, 256>>>((const float4*)wq, wqh, wql, nw4);
    split_kernel<<<(nw4 + 255) / 256, 256>>>((const float4*)wk, wkh, wkl, nw4);
    split_kernel<<<(nw4 + 255) / 256, 256>>>((const float4*)wv, wvh, wvl, nw4);
    split_kernel<<<(nw4 + 255) / 256, 256>>>((const float4*)wo, woh, wol, nw4);

    dim3 gg(HIDDEN / GBN, MROWS / GBM); // (16, 32)
    gemm3_kernel<<<gg, 256>>>(xh, xl, wqh, wql, q);
    gemm3_kernel<<<gg, 256>>>(xh, xl, wkh, wkl, k);
    gemm3_kernel<<<gg, 256>>>(xh, xl, wvh, wvl, v);

    rope_split_kernel<<<(MROWS * HEADS * 64) / 256, 256>>>(q, k, qh, ql, kh, kl);
    vt_split_kernel<<<dim3(SEQL / 32, HD / 32, NBATCH * HEADS), dim3(32, 8)>>>(v, vth, vtl);

    cudaFuncSetAttribute(flash_mma_kernel, cudaFuncAttributeMaxDynamicSharedMemorySize, FLASH_SMEM);
    flash_mma_kernel<<<dim3(SEQL / 128, HEADS, NBATCH), 256, FLASH_SMEM>>>(
        qh, ql, kh, kl, vth, vtl, o);

    split_kernel<<<(nx4 + 255) / 256, 256>>>((const float4*)o, oh, ol, nx4);
    gemm3_kernel<<<gg, 256>>>(oh, ol, woh, wol, out);
}

// round 11
// speedup vs baseline: 1.3971x; 1.0227x over previous
#include <cuda_runtime.h>
#include <cuda_bf16.h>
#include <math.h>
#include <stdint.h>

#define HIDDEN 2048
#define HEADS 16
#define HD 128
#define SEQL 2048
#define NBATCH 2
#define MROWS (NBATCH * SEQL) // 4096
#define KDIM 2048

// ---------------------------------------------------------------------------
// Scratch: __device__ globals (no cudaMalloc allowed)
// ---------------------------------------------------------------------------
__device__ float g_q[(size_t)MROWS * HIDDEN];
__device__ float g_k[(size_t)MROWS * HIDDEN];
__device__ float g_v[(size_t)MROWS * HIDDEN];
__device__ float g_o[(size_t)MROWS * HIDDEN];

__device__ __nv_bfloat16 g_xh[(size_t)MROWS * HIDDEN];
__device__ __nv_bfloat16 g_xl[(size_t)MROWS * HIDDEN];
__device__ __nv_bfloat16 g_oh[(size_t)MROWS * HIDDEN];
__device__ __nv_bfloat16 g_ol[(size_t)MROWS * HIDDEN];
__device__ __nv_bfloat16 g_wqh[(size_t)HIDDEN * HIDDEN];
__device__ __nv_bfloat16 g_wql[(size_t)HIDDEN * HIDDEN];
__device__ __nv_bfloat16 g_wkh[(size_t)HIDDEN * HIDDEN];
__device__ __nv_bfloat16 g_wkl[(size_t)HIDDEN * HIDDEN];
__device__ __nv_bfloat16 g_wvh[(size_t)HIDDEN * HIDDEN];
__device__ __nv_bfloat16 g_wvl[(size_t)HIDDEN * HIDDEN];
__device__ __nv_bfloat16 g_woh[(size_t)HIDDEN * HIDDEN];
__device__ __nv_bfloat16 g_wol[(size_t)HIDDEN * HIDDEN];

// bf16 split Q/K (post-RoPE) and transposed V for flash
__device__ __nv_bfloat16 g_qh[(size_t)MROWS * HIDDEN];
__device__ __nv_bfloat16 g_ql[(size_t)MROWS * HIDDEN];
__device__ __nv_bfloat16 g_kh[(size_t)MROWS * HIDDEN];
__device__ __nv_bfloat16 g_kl[(size_t)MROWS * HIDDEN];
__device__ __nv_bfloat16 g_vth[(size_t)MROWS * HIDDEN];
__device__ __nv_bfloat16 g_vtl[(size_t)MROWS * HIDDEN];

// ---------------------------------------------------------------------------
__device__ __forceinline__ void mma16816(float* c, const uint32_t* a, const uint32_t* b)
{
    asm volatile(
        "mma.sync.aligned.m16n8k16.row.col.f32.bf16.bf16.f32 "
        "{%0,%1,%2,%3}, {%4,%5,%6,%7}, {%8,%9}, {%0,%1,%2,%3};"
        : "+f"(c[0]), "+f"(c[1]), "+f"(c[2]), "+f"(c[3])
        : "r"(a[0]), "r"(a[1]), "r"(a[2]), "r"(a[3]), "r"(b[0]), "r"(b[1]));
}

#define LDSM4(r0, r1, r2, r3, addr) \
    asm volatile("ldmatrix.sync.aligned.m8n8.x4.shared.b16 {%0,%1,%2,%3}, [%4];" \
                 : "=r"(r0), "=r"(r1), "=r"(r2), "=r"(r3) : "r"(addr))

// ---------------------------------------------------------------------------
// Split fp32 -> (bf16 hi, bf16 lo) elementwise, vectorized x4
// ---------------------------------------------------------------------------
__global__ void split_kernel(const float4* __restrict__ a,
                             __nv_bfloat16* __restrict__ hi,
                             __nv_bfloat16* __restrict__ lo, int n4)
{
    int i = blockIdx.x * blockDim.x + threadIdx.x;
    if (i >= n4) return;
    float4 v = a[i];
    __nv_bfloat16 h0 = __float2bfloat16(v.x);
    __nv_bfloat16 h1 = __float2bfloat16(v.y);
    __nv_bfloat16 h2 = __float2bfloat16(v.z);
    __nv_bfloat16 h3 = __float2bfloat16(v.w);
    __nv_bfloat16 l0 = __float2bfloat16(v.x - __bfloat162float(h0));
    __nv_bfloat16 l1 = __float2bfloat16(v.y - __bfloat162float(h1));
    __nv_bfloat16 l2 = __float2bfloat16(v.z - __bfloat162float(h2));
    __nv_bfloat16 l3 = __float2bfloat16(v.w - __bfloat162float(h3));
    ushort4 hv, lv;
    hv.x = __bfloat16_as_ushort(h0); hv.y = __bfloat16_as_ushort(h1);
    hv.z = __bfloat16_as_ushort(h2); hv.w = __bfloat16_as_ushort(h3);
    lv.x = __bfloat16_as_ushort(l0); lv.y = __bfloat16_as_ushort(l1);
    lv.z = __bfloat16_as_ushort(l2); lv.w = __bfloat16_as_ushort(l3);
    *(ushort4*)(hi + (size_t)i * 4) = hv;
    *(ushort4*)(lo + (size_t)i * 4) = lv;
}

// ---------------------------------------------------------------------------
// bf16x3 GEMM (R10-validated body). grid.z selects among up to 3 (B, C) sets
// sharing the same A — one launch for Q/K/V amortizes tail waves and reuses
// A tiles in L2.
// ---------------------------------------------------------------------------
#define GBM 128
#define GBN 128
#define GBK 32
#define LDS_W 40
#define TILE_B2 (GBM * LDS_W * 2)   // bytes per buffer = 10240
#define NCHUNK (3 * KDIM / GBK)     // 192

__global__ __launch_bounds__(256) void gemm3_kernel(
    const __nv_bfloat16* __restrict__ Ah, const __nv_bfloat16* __restrict__ Al,
    const __nv_bfloat16* __restrict__ Bh0, const __nv_bfloat16* __restrict__ Bl0,
    float* __restrict__ C0,
    const __nv_bfloat16* __restrict__ Bh1, const __nv_bfloat16* __restrict__ Bl1,
    float* __restrict__ C1,
    const __nv_bfloat16* __restrict__ Bh2, const __nv_bfloat16* __restrict__ Bl2,
    float* __restrict__ C2)
{
    const int z = blockIdx.z;
    const __nv_bfloat16* BhP = (z == 0) ? Bh0 : (z == 1) ? Bh1 : Bh2;
    const __nv_bfloat16* BlP = (z == 0) ? Bl0 : (z == 1) ? Bl1 : Bl2;
    float* C = (z == 0) ? C0 : (z == 1) ? C1 : C2;

    __shared__ __nv_bfloat16 sA[2][GBM * LDS_W];
    __shared__ __nv_bfloat16 sB[2][GBN * LDS_W];

    const int tid = threadIdx.x;
    const int lane = tid & 31;
    const int wid = tid >> 5;
    const int wm = (wid & 3) * 32;
    const int wn = (wid >> 2) * 64;
    const int g = lane >> 2;
    const int t = lane & 3;
    const int lrow = lane & 15;          // ldmatrix source row
    const int lsel = (lane >> 4) * 8;    // ldmatrix col half

    const int bm = blockIdx.y * GBM;
    const int bn = blockIdx.x * GBN;

    const int grow = tid >> 1;
    const int gcol = (tid & 1) * 16;

    const uint32_t sAu = (uint32_t)__cvta_generic_to_shared(&sA[0][0]);
    const uint32_t sBu = (uint32_t)__cvta_generic_to_shared(&sB[0][0]);

    float acc[2][8][4];
#pragma unroll
    for (int i = 0; i < 2; i++)
#pragma unroll
        for (int j = 0; j < 8; j++)
#pragma unroll
            for (int r = 0; r < 4; r++) acc[i][j][r] = 0.f;

    auto fetch = [&](int c, uint4& ra0, uint4& ra1, uint4& rb0, uint4& rb1) {
        const int pass = c >> 6;
        const int k0 = (c & 63) * GBK;
        const __nv_bfloat16* Ap = (pass == 2) ? Al : Ah;
        const __nv_bfloat16* Bp = (pass == 1) ? BlP : BhP;
        const size_t ga = (size_t)(bm + grow) * KDIM + k0 + gcol;
        const size_t gb = (size_t)(bn + grow) * KDIM + k0 + gcol;
        ra0 = *(const uint4*)(Ap + ga);
        ra1 = *(const uint4*)(Ap + ga + 8);
        rb0 = *(const uint4*)(Bp + gb);
        rb1 = *(const uint4*)(Bp + gb + 8);
    };
    auto store = [&](int buf, const uint4& ra0, const uint4& ra1,
                     const uint4& rb0, const uint4& rb1) {
        __nv_bfloat16* pa = &sA[buf][grow * LDS_W + gcol];
        __nv_bfloat16* pb = &sB[buf][grow * LDS_W + gcol];
        *(uint4*)pa = ra0;
        *(uint4*)(pa + 8) = ra1;
        *(uint4*)pb = rb0;
        *(uint4*)(pb + 8) = rb1;
    };

    {
        uint4 ra0, ra1, rb0, rb1;
        fetch(0, ra0, ra1, rb0, rb1);
        store(0, ra0, ra1, rb0, rb1);
    }
    __syncthreads();

    for (int c = 0; c < NCHUNK; c++) {
        const int buf = c & 1;
        const bool more = (c + 1 < NCHUNK);
        uint4 ra0, ra1, rb0, rb1;
        if (more) fetch(c + 1, ra0, ra1, rb0, rb1);

        const uint32_t sa = sAu + (uint32_t)buf * TILE_B2;
        const uint32_t sb = sBu + (uint32_t)buf * TILE_B2;
#pragma unroll
        for (int kk = 0; kk < GBK; kk += 16) {
            uint32_t af[2][4];
#pragma unroll
            for (int mt = 0; mt < 2; mt++) {
                const uint32_t ra = sa + (uint32_t)((wm + mt * 16 + lrow) * LDS_W + kk + lsel) * 2;
                LDSM4(af[mt][0], af[mt][1], af[mt][2], af[mt][3], ra);
            }
            uint32_t bfr[8][2];
#pragma unroll
            for (int p = 0; p < 4; p++) {
                const uint32_t rb = sb + (uint32_t)((wn + p * 16 + lrow) * LDS_W + kk + lsel) * 2;
                uint32_t r0, r1, r2, r3;
                LDSM4(r0, r1, r2, r3, rb);
                bfr[2 * p][0] = r0; bfr[2 * p + 1][0] = r1;
                bfr[2 * p][1] = r2; bfr[2 * p + 1][1] = r3;
            }
#pragma unroll
            for (int mt = 0; mt < 2; mt++)
#pragma unroll
                for (int nt = 0; nt < 8; nt++)
                    mma16816(acc[mt][nt], af[mt], bfr[nt]);
        }

        if (more) store(buf ^ 1, ra0, ra1, rb0, rb1);
        __syncthreads();
    }

#pragma unroll
    for (int mt = 0; mt < 2; mt++) {
        const int r0 = bm + wm + mt * 16 + g;
#pragma unroll
        for (int nt = 0; nt < 8; nt++) {
            const int col = bn + wn + nt * 8 + 2 * t;
            *(float2*)&C[(size_t)r0 * HIDDEN + col] = make_float2(acc[mt][nt][0], acc[mt][nt][1]);
            *(float2*)&C[(size_t)(r0 + 8) * HIDDEN + col] = make_float2(acc[mt][nt][2], acc[mt][nt][3]);
        }
    }
}

// ---------------------------------------------------------------------------
// RoPE + split to bf16 hi/lo for Q and K.
// ---------------------------------------------------------------------------
__global__ void rope_split_kernel(const float* __restrict__ q, const float* __restrict__ k,
                                  __nv_bfloat16* __restrict__ qh, __nv_bfloat16* __restrict__ ql,
                                  __nv_bfloat16* __restrict__ kh, __nv_bfloat16* __restrict__ kl)
{
    int idx = blockIdx.x * blockDim.x + threadIdx.x;
    int d = idx & 63;
    int m = idx >> 10;
    int l = m & (SEQL - 1);
    int h = (idx >> 6) & (HEADS - 1);

    float e = (2.0f * (float)d) / 128.0f;
    float inv = 1.0f / powf(10000.0f, e);
    float ang = (float)l * inv;
    float s, c;
    sincosf(ang, &s, &c);

    size_t base = (size_t)m * HIDDEN + h * HD + d;
    float q1 = q[base], q2 = q[base + 64];
    float k1 = k[base], k2 = k[base + 64];
    float qa = q1 * c - q2 * s;
    float qb = q2 * c + q1 * s;
    float ka = k1 * c - k2 * s;
    float kb = k2 * c + k1 * s;

    __nv_bfloat16 t0;
    t0 = __float2bfloat16(qa); qh[base] = t0;      ql[base] = __float2bfloat16(qa - __bfloat162float(t0));
    t0 = __float2bfloat16(qb); qh[base + 64] = t0; ql[base + 64] = __float2bfloat16(qb - __bfloat162float(t0));
    t0 = __float2bfloat16(ka); kh[base] = t0;      kl[base] = __float2bfloat16(ka - __bfloat162float(t0));
    t0 = __float2bfloat16(kb); kh[base + 64] = t0; kl[base + 64] = __float2bfloat16(kb - __bfloat162float(t0));
}

// ---------------------------------------------------------------------------
// V transpose + split
// ---------------------------------------------------------------------------
__global__ __launch_bounds__(256) void vt_split_kernel(
    const float* __restrict__ v,
    __nv_bfloat16* __restrict__ vth, __nv_bfloat16* __restrict__ vtl)
{
    __shared__ float tile[32][33];
    const int bh = blockIdx.z;
    const int b = bh >> 4, h = bh & 15;
    const int l0 = blockIdx.x * 32, d0 = blockIdx.y * 32;
    const int tx = threadIdx.x, ty = threadIdx.y;

#pragma unroll
    for (int i = 0; i < 4; i++) {
        int r = ty + i * 8;
        tile[r][tx] = v[(size_t)(b * SEQL + l0 + r) * HIDDEN + h * HD + d0 + tx];
    }
    __syncthreads();
#pragma unroll
    for (int i = 0; i < 4; i++) {
        int r = ty + i * 8;
        float f = tile[tx][r];
        __nv_bfloat16 hi = __float2bfloat16(f);
        size_t o = ((size_t)((b * HEADS + h) * HD + d0 + r)) * SEQL + l0 + tx;
        vth[o] = hi;
        vtl[o] = __float2bfloat16(f - __bfloat162float(hi));
    }
}

// ---------------------------------------------------------------------------
// Flash attention on tensor cores + ldmatrix fragment loads
// ---------------------------------------------------------------------------
#define QW 136
#define VW 72
#define OQH 0
#define OQL 17408
#define OKH 34816
#define OKL 43520
#define OVH 52224
#define OVL 61440
#define FLASH_SMEM (70656 * 2)

__device__ __forceinline__ void pack_pair(float a, float b, uint32_t& hi_pack, uint32_t& lo_pack)
{
    uint32_t ph;
    asm("cvt.rn.bf16x2.f32 %0, %1, %2;" : "=r"(ph) : "f"(b), "f"(a));
    float ra = a - __uint_as_float(ph << 16);
    float rb = b - __uint_as_float(ph & 0xffff0000u);
    asm("cvt.rn.bf16x2.f32 %0, %1, %2;" : "=r"(lo_pack) : "f"(rb), "f"(ra));
    hi_pack = ph;
}

__global__ __launch_bounds__(256) void flash_mma_kernel(
    const __nv_bfloat16* __restrict__ Qh, const __nv_bfloat16* __restrict__ Ql,
    const __nv_bfloat16* __restrict__ Kh, const __nv_bfloat16* __restrict__ Kl,
    const __nv_bfloat16* __restrict__ Vth, const __nv_bfloat16* __restrict__ Vtl,
    float* __restrict__ O)
{
    extern __shared__ __nv_bfloat16 fs[];
    __nv_bfloat16* sQh = fs + OQH;
    __nv_bfloat16* sQl = fs + OQL;
    __nv_bfloat16* sKh = fs + OKH;
    __nv_bfloat16* sKl = fs + OKL;
    __nv_bfloat16* sVh = fs + OVH;
    __nv_bfloat16* sVl = fs + OVL;

    const uint32_t fsU = (uint32_t)__cvta_generic_to_shared(fs);
    const uint32_t sQhU = fsU + OQH * 2;
    const uint32_t sQlU = fsU + OQL * 2;
    const uint32_t sKhU = fsU + OKH * 2;
    const uint32_t sKlU = fsU + OKL * 2;
    const uint32_t sVhU = fsU + OVH * 2;
    const uint32_t sVlU = fsU + OVL * 2;

    const int qt = blockIdx.x, h = blockIdx.y, b = blockIdx.z;
    const int tid = threadIdx.x, lane = tid & 31, wid = tid >> 5;
    const int g = lane >> 2, t = lane & 3;
    const int lrow = lane & 15;
    const int lsel = (lane >> 4) * 8;
    const int wm = wid * 16;
    const float scale = 0.0883883476483184f;

    {
        const size_t base = (size_t)(b * SEQL + qt * 128) * HIDDEN + h * HD;
#pragma unroll
        for (int it = 0; it < 8; it++) {
            int id = tid + it * 256;
            int r = id >> 4, c8 = (id & 15) * 8;
            *(uint4*)&sQh[r * QW + c8] = *(const uint4*)&Qh[base + (size_t)r * HIDDEN + c8];
            *(uint4*)&sQl[r * QW + c8] = *(const uint4*)&Ql[base + (size_t)r * HIDDEN + c8];
        }
    }

    float m0 = -1e30f, m1 = -1e30f, l0 = 0.f, l1 = 0.f;
    float oacc[16][4];
#pragma unroll
    for (int nt = 0; nt < 16; nt++)
#pragma unroll
        for (int r = 0; r < 4; r++) oacc[nt][r] = 0.f;

    const int nkt = 2 * qt + 2;
    for (int kt = 0; kt < nkt; kt++) {
        __syncthreads();
#pragma unroll
        for (int it = 0; it < 4; it++) {
            int id = tid + it * 256;
            int r = id >> 4, c8 = (id & 15) * 8;
            size_t gk = (size_t)(b * SEQL + kt * 64 + r) * HIDDEN + h * HD + c8;
            *(uint4*)&sKh[r * QW + c8] = *(const uint4*)&Kh[gk];
            *(uint4*)&sKl[r * QW + c8] = *(const uint4*)&Kl[gk];
            int rv = id >> 3, cv = (id & 7) * 8;
            size_t gv = (size_t)((b * HEADS + h) * HD + rv) * SEQL + kt * 64 + cv;
            *(uint4*)&sVh[rv * VW + cv] = *(const uint4*)&Vth[gv];
            *(uint4*)&sVl[rv * VW + cv] = *(const uint4*)&Vtl[gv];
        }
        __syncthreads();

        float sacc[8][4];
#pragma unroll
        for (int nt = 0; nt < 8; nt++)
#pragma unroll
            for (int r = 0; r < 4; r++) sacc[nt][r] = 0.f;

#pragma unroll
        for (int kc = 0; kc < 8; kc++) {
            const int kk = kc * 16;
            uint32_t aqh[4], aql[4];
            const uint32_t aoff = (uint32_t)((wm + lrow) * QW + kk + lsel) * 2;
            LDSM4(aqh[0], aqh[1], aqh[2], aqh[3], sQhU + aoff);
            LDSM4(aql[0], aql[1], aql[2], aql[3], sQlU + aoff);
            uint32_t bh[8][2], bl[8][2];
#pragma unroll
            for (int p = 0; p < 4; p++) {
                const uint32_t boff = (uint32_t)((p * 16 + lrow) * QW + kk + lsel) * 2;
                uint32_t r0, r1, r2, r3;
                LDSM4(r0, r1, r2, r3, sKhU + boff);
                bh[2 * p][0] = r0; bh[2 * p + 1][0] = r1;
                bh[2 * p][1] = r2; bh[2 * p + 1][1] = r3;
                LDSM4(r0, r1, r2, r3, sKlU + boff);
                bl[2 * p][0] = r0; bl[2 * p + 1][0] = r1;
                bl[2 * p][1] = r2; bl[2 * p + 1][1] = r3;
            }
#pragma unroll
            for (int nt = 0; nt < 8; nt++) {
                mma16816(sacc[nt], aqh, bh[nt]);
                mma16816(sacc[nt], aqh, bl[nt]);
                mma16816(sacc[nt], aql, bh[nt]);
            }
        }

        const int row0 = qt * 128 + wm + g;
        const int row1 = row0 + 8;
#pragma unroll
        for (int nt = 0; nt < 8; nt++) {
            sacc[nt][0] *= scale; sacc[nt][1] *= scale;
            sacc[nt][2] *= scale; sacc[nt][3] *= scale;
        }
        if (kt * 64 + 63 > qt * 128 + wm) {
#pragma unroll
            for (int nt = 0; nt < 8; nt++) {
                const int col = kt * 64 + nt * 8 + 2 * t;
                if (col > row0)     sacc[nt][0] = -1e30f;
                if (col + 1 > row0) sacc[nt][1] = -1e30f;
                if (col > row1)     sacc[nt][2] = -1e30f;
                if (col + 1 > row1) sacc[nt][3] = -1e30f;
            }
        }

        float mt0 = -1e30f, mt1 = -1e30f;
#pragma unroll
        for (int nt = 0; nt < 8; nt++) {
            mt0 = fmaxf(mt0, fmaxf(sacc[nt][0], sacc[nt][1]));
            mt1 = fmaxf(mt1, fmaxf(sacc[nt][2], sacc[nt][3]));
        }
        mt0 = fmaxf(mt0, __shfl_xor_sync(0xffffffffu, mt0, 1));
        mt0 = fmaxf(mt0, __shfl_xor_sync(0xffffffffu, mt0, 2));
        mt1 = fmaxf(mt1, __shfl_xor_sync(0xffffffffu, mt1, 1));
        mt1 = fmaxf(mt1, __shfl_xor_sync(0xffffffffu, mt1, 2));

        const float nm0 = fmaxf(m0, mt0), nm1 = fmaxf(m1, mt1);
        const float alpha0 = __expf(m0 - nm0), alpha1 = __expf(m1 - nm1);
        float ps0 = 0.f, ps1 = 0.f;
#pragma unroll
        for (int nt = 0; nt < 8; nt++) {
            sacc[nt][0] = __expf(sacc[nt][0] - nm0);
            sacc[nt][1] = __expf(sacc[nt][1] - nm0);
            sacc[nt][2] = __expf(sacc[nt][2] - nm1);
            sacc[nt][3] = __expf(sacc[nt][3] - nm1);
            ps0 += sacc[nt][0] + sacc[nt][1];
            ps1 += sacc[nt][2] + sacc[nt][3];
        }
        ps0 += __shfl_xor_sync(0xffffffffu, ps0, 1);
        ps0 += __shfl_xor_sync(0xffffffffu, ps0, 2);
        ps1 += __shfl_xor_sync(0xffffffffu, ps1, 1);
        ps1 += __shfl_xor_sync(0xffffffffu, ps1, 2);
        l0 = alpha0 * l0 + ps0; m0 = nm0;
        l1 = alpha1 * l1 + ps1; m1 = nm1;
#pragma unroll
        for (int nt = 0; nt < 16; nt++) {
            oacc[nt][0] *= alpha0; oacc[nt][1] *= alpha0;
            oacc[nt][2] *= alpha1; oacc[nt][3] *= alpha1;
        }

        uint32_t ph[4][4], pl[4][4];
#pragma unroll
        for (int kc = 0; kc < 4; kc++) {
            const int j0 = 2 * kc, j1 = 2 * kc + 1;
            pack_pair(sacc[j0][0], sacc[j0][1], ph[kc][0], pl[kc][0]);
            pack_pair(sacc[j0][2], sacc[j0][3], ph[kc][1], pl[kc][1]);
            pack_pair(sacc[j1][0], sacc[j1][1], ph[kc][2], pl[kc][2]);
            pack_pair(sacc[j1][2], sacc[j1][3], ph[kc][3], pl[kc][3]);
        }

#pragma unroll
        for (int kc = 0; kc < 4; kc++) {
#pragma unroll
            for (int p = 0; p < 8; p++) {
                const uint32_t voff = (uint32_t)((p * 16 + lrow) * VW + kc * 16 + lsel) * 2;
                uint32_t vh0[2], vh1[2], vl0[2], vl1[2];
                uint32_t r0, r1, r2, r3;
                LDSM4(r0, r1, r2, r3, sVhU + voff);
                vh0[0] = r0; vh1[0] = r1; vh0[1] = r2; vh1[1] = r3;
                LDSM4(r0, r1, r2, r3, sVlU + voff);
                vl0[0] = r0; vl1[0] = r1; vl0[1] = r2; vl1[1] = r3;
                mma16816(oacc[2 * p], ph[kc], vh0);
                mma16816(oacc[2 * p], ph[kc], vl0);
                mma16816(oacc[2 * p], pl[kc], vh0);
                mma16816(oacc[2 * p + 1], ph[kc], vh1);
                mma16816(oacc[2 * p + 1], ph[kc], vl1);
                mma16816(oacc[2 * p + 1], pl[kc], vh1);
            }
        }
    }

    const float i0 = 1.0f / l0, i1 = 1.0f / l1;
    const size_t rbase = (size_t)(b * SEQL + qt * 128 + wm + g) * HIDDEN + h * HD + 2 * t;
#pragma unroll
    for (int nt = 0; nt < 16; nt++) {
        *(float2*)&O[rbase + nt * 8] = make_float2(oacc[nt][0] * i0, oacc[nt][1] * i0);
        *(float2*)&O[rbase + 8 * HIDDEN + nt * 8] = make_float2(oacc[nt][2] * i1, oacc[nt][3] * i1);
    }
}

// ---------------------------------------------------------------------------
extern "C" void kernel_launch(void* const* d_in, const int* in_sizes, int n_in,
                              void* d_out, int out_size)
{
    const float* x  = (const float*)d_in[0];
    const float* wq = (const float*)d_in[1];
    const float* wk = (const float*)d_in[2];
    const float* wv = (const float*)d_in[3];
    const float* wo = (const float*)d_in[4];
    float* out = (float*)d_out;

    float *q, *k, *v, *o;
    cudaGetSymbolAddress((void**)&q, g_q);
    cudaGetSymbolAddress((void**)&k, g_k);
    cudaGetSymbolAddress((void**)&v, g_v);
    cudaGetSymbolAddress((void**)&o, g_o);

    __nv_bfloat16 *xh, *xl, *oh, *ol;
    __nv_bfloat16 *wqh, *wql, *wkh, *wkl, *wvh, *wvl, *woh, *wol;
    __nv_bfloat16 *qh, *ql, *kh, *kl, *vth, *vtl;
    cudaGetSymbolAddress((void**)&xh, g_xh);
    cudaGetSymbolAddress((void**)&xl, g_xl);
    cudaGetSymbolAddress((void**)&oh, g_oh);
    cudaGetSymbolAddress((void**)&ol, g_ol);
    cudaGetSymbolAddress((void**)&wqh, g_wqh);
    cudaGetSymbolAddress((void**)&wql, g_wql);
    cudaGetSymbolAddress((void**)&wkh, g_wkh);
    cudaGetSymbolAddress((void**)&wkl, g_wkl);
    cudaGetSymbolAddress((void**)&wvh, g_wvh);
    cudaGetSymbolAddress((void**)&wvl, g_wvl);
    cudaGetSymbolAddress((void**)&woh, g_woh);
    cudaGetSymbolAddress((void**)&wol, g_wol);
    cudaGetSymbolAddress((void**)&qh, g_qh);
    cudaGetSymbolAddress((void**)&ql, g_ql);
    cudaGetSymbolAddress((void**)&kh, g_kh);
    cudaGetSymbolAddress((void**)&kl, g_kl);
    cudaGetSymbolAddress((void**)&vth, g_vth);
    cudaGetSymbolAddress((void**)&vtl, g_vtl);

    const int nx4 = MROWS * HIDDEN / 4;
    const int nw4 = HIDDEN * HIDDEN / 4;
    split_kernel<<<(nx4 + 255) / 256, 256>>>((const float4*)x, xh, xl, nx4);
    split_kernel<<<(nw4 + 255) / 256, 256>>>((const float4*)wq, wqh, wql, nw4);
    split_kernel<<<(nw4 + 255) / 256, 256>>>((const float4*)wk, wkh, wkl, nw4);
    split_kernel<<<(nw4 + 255) / 256, 256>>>((const float4*)wv, wvh, wvl, nw4);
    split_kernel<<<(nw4 + 255) / 256, 256>>>((const float4*)wo, woh, wol, nw4);

    // QKV: one launch, grid.z picks the weight/output set
    gemm3_kernel<<<dim3(HIDDEN / GBN, MROWS / GBM, 3), 256>>>(
        xh, xl, wqh, wql, q, wkh, wkl, k, wvh, wvl, v);

    rope_split_kernel<<<(MROWS * HEADS * 64) / 256, 256>>>(q, k, qh, ql, kh, kl);
    vt_split_kernel<<<dim3(SEQL / 32, HD / 32, NBATCH * HEADS), dim3(32, 8)>>>(v, vth, vtl);

    cudaFuncSetAttribute(flash_mma_kernel, cudaFuncAttributeMaxDynamicSharedMemorySize, FLASH_SMEM);
    flash_mma_kernel<<<dim3(SEQL / 128, HEADS, NBATCH), 256, FLASH_SMEM>>>(
        qh, ql, kh, kl, vth, vtl, o);

    split_kernel<<<(nx4 + 255) / 256, 256>>>((const float4*)o, oh, ol, nx4);
    gemm3_kernel<<<dim3(HIDDEN / GBN, MROWS / GBM, 1), 256>>>(
        oh, ol, woh, wol, out, woh, wol, out, woh, wol, out);
}

// round 12
// speedup vs baseline: 1.6292x; 1.1661x over previous
#include <cuda_runtime.h>
#include <cuda_bf16.h>
#include <cuda_fp16.h>
#include <math.h>
#include <stdint.h>

#define HIDDEN 2048
#define HEADS 16
#define HD 128
#define SEQL 2048
#define NBATCH 2
#define MROWS (NBATCH * SEQL) // 4096
#define KDIM 2048

// ---------------------------------------------------------------------------
// Scratch: __device__ globals (no cudaMalloc allowed)
// ---------------------------------------------------------------------------
__device__ float g_q[(size_t)MROWS * HIDDEN];
__device__ float g_k[(size_t)MROWS * HIDDEN];
__device__ float g_v[(size_t)MROWS * HIDDEN];
__device__ float g_o[(size_t)MROWS * HIDDEN];

// bf16 3-term operands (Q,K projections)
__device__ __nv_bfloat16 g_xh[(size_t)MROWS * HIDDEN];
__device__ __nv_bfloat16 g_xl[(size_t)MROWS * HIDDEN];
__device__ __nv_bfloat16 g_wqh[(size_t)HIDDEN * HIDDEN];
__device__ __nv_bfloat16 g_wql[(size_t)HIDDEN * HIDDEN];
__device__ __nv_bfloat16 g_wkh[(size_t)HIDDEN * HIDDEN];
__device__ __nv_bfloat16 g_wkl[(size_t)HIDDEN * HIDDEN];

// fp16 2-term operands (V, O projections)
__device__ __half g_xh16[(size_t)MROWS * HIDDEN];
__device__ __half g_xl16[(size_t)MROWS * HIDDEN];
__device__ __half g_oh16[(size_t)MROWS * HIDDEN];
__device__ __half g_ol16[(size_t)MROWS * HIDDEN];
__device__ __half g_wvh16[(size_t)HIDDEN * HIDDEN];
__device__ __half g_woh16[(size_t)HIDDEN * HIDDEN];

// bf16 split Q/K (post-RoPE) and fp16 transposed V for flash
__device__ __nv_bfloat16 g_qh[(size_t)MROWS * HIDDEN];
__device__ __nv_bfloat16 g_ql[(size_t)MROWS * HIDDEN];
__device__ __nv_bfloat16 g_kh[(size_t)MROWS * HIDDEN];
__device__ __nv_bfloat16 g_kl[(size_t)MROWS * HIDDEN];
__device__ __half g_vt16[(size_t)MROWS * HIDDEN];

// ---------------------------------------------------------------------------
__device__ __forceinline__ void mma16816(float* c, const uint32_t* a, const uint32_t* b)
{
    asm volatile(
        "mma.sync.aligned.m16n8k16.row.col.f32.bf16.bf16.f32 "
        "{%0,%1,%2,%3}, {%4,%5,%6,%7}, {%8,%9}, {%0,%1,%2,%3};"
        : "+f"(c[0]), "+f"(c[1]), "+f"(c[2]), "+f"(c[3])
        : "r"(a[0]), "r"(a[1]), "r"(a[2]), "r"(a[3]), "r"(b[0]), "r"(b[1]));
}

__device__ __forceinline__ void mma16816h(float* c, const uint32_t* a, const uint32_t* b)
{
    asm volatile(
        "mma.sync.aligned.m16n8k16.row.col.f32.f16.f16.f32 "
        "{%0,%1,%2,%3}, {%4,%5,%6,%7}, {%8,%9}, {%0,%1,%2,%3};"
        : "+f"(c[0]), "+f"(c[1]), "+f"(c[2]), "+f"(c[3])
        : "r"(a[0]), "r"(a[1]), "r"(a[2]), "r"(a[3]), "r"(b[0]), "r"(b[1]));
}

#define LDSM4(r0, r1, r2, r3, addr) \
    asm volatile("ldmatrix.sync.aligned.m8n8.x4.shared.b16 {%0,%1,%2,%3}, [%4];" \
                 : "=r"(r0), "=r"(r1), "=r"(r2), "=r"(r3) : "r"(addr))

// ---------------------------------------------------------------------------
// Split fp32 -> (bf16 hi, bf16 lo)
// ---------------------------------------------------------------------------
__global__ void split_kernel(const float4* __restrict__ a,
                             __nv_bfloat16* __restrict__ hi,
                             __nv_bfloat16* __restrict__ lo, int n4)
{
    int i = blockIdx.x * blockDim.x + threadIdx.x;
    if (i >= n4) return;
    float4 v = a[i];
    __nv_bfloat16 h0 = __float2bfloat16(v.x);
    __nv_bfloat16 h1 = __float2bfloat16(v.y);
    __nv_bfloat16 h2 = __float2bfloat16(v.z);
    __nv_bfloat16 h3 = __float2bfloat16(v.w);
    ushort4 hv, lv;
    hv.x = __bfloat16_as_ushort(h0); hv.y = __bfloat16_as_ushort(h1);
    hv.z = __bfloat16_as_ushort(h2); hv.w = __bfloat16_as_ushort(h3);
    lv.x = __bfloat16_as_ushort(__float2bfloat16(v.x - __bfloat162float(h0)));
    lv.y = __bfloat16_as_ushort(__float2bfloat16(v.y - __bfloat162float(h1)));
    lv.z = __bfloat16_as_ushort(__float2bfloat16(v.z - __bfloat162float(h2)));
    lv.w = __bfloat16_as_ushort(__float2bfloat16(v.w - __bfloat162float(h3)));
    *(ushort4*)(hi + (size_t)i * 4) = hv;
    *(ushort4*)(lo + (size_t)i * 4) = lv;
}

// Split fp32 -> (fp16 hi, fp16 lo)
__global__ void split2h_kernel(const float4* __restrict__ a,
                               __half* __restrict__ hi,
                               __half* __restrict__ lo, int n4)
{
    int i = blockIdx.x * blockDim.x + threadIdx.x;
    if (i >= n4) return;
    float4 v = a[i];
    __half h0 = __float2half_rn(v.x);
    __half h1 = __float2half_rn(v.y);
    __half h2 = __float2half_rn(v.z);
    __half h3 = __float2half_rn(v.w);
    ushort4 hv, lv;
    hv.x = __half_as_ushort(h0); hv.y = __half_as_ushort(h1);
    hv.z = __half_as_ushort(h2); hv.w = __half_as_ushort(h3);
    lv.x = __half_as_ushort(__float2half_rn(v.x - __half2float(h0)));
    lv.y = __half_as_ushort(__float2half_rn(v.y - __half2float(h1)));
    lv.z = __half_as_ushort(__float2half_rn(v.z - __half2float(h2)));
    lv.w = __half_as_ushort(__float2half_rn(v.w - __half2float(h3)));
    *(ushort4*)(hi + (size_t)i * 4) = hv;
    *(ushort4*)(lo + (size_t)i * 4) = lv;
}

// Round fp32 -> fp16 only
__global__ void round_h_kernel(const float4* __restrict__ a,
                               __half* __restrict__ hi, int n4)
{
    int i = blockIdx.x * blockDim.x + threadIdx.x;
    if (i >= n4) return;
    float4 v = a[i];
    ushort4 hv;
    hv.x = __half_as_ushort(__float2half_rn(v.x));
    hv.y = __half_as_ushort(__float2half_rn(v.y));
    hv.z = __half_as_ushort(__float2half_rn(v.z));
    hv.w = __half_as_ushort(__float2half_rn(v.w));
    *(ushort4*)(hi + (size_t)i * 4) = hv;
}

// ---------------------------------------------------------------------------
// bf16x3 GEMM (validated). grid.z selects among (B, C) sets sharing A.
// ---------------------------------------------------------------------------
#define GBM 128
#define GBN 128
#define GBK 32
#define LDS_W 40
#define TILE_B2 (GBM * LDS_W * 2)   // bytes per buffer = 10240
#define NCHUNK (3 * KDIM / GBK)     // 192
#define NCHUNK2 (2 * KDIM / GBK)    // 128

__global__ __launch_bounds__(256) void gemm3_kernel(
    const __nv_bfloat16* __restrict__ Ah, const __nv_bfloat16* __restrict__ Al,
    const __nv_bfloat16* __restrict__ Bh0, const __nv_bfloat16* __restrict__ Bl0,
    float* __restrict__ C0,
    const __nv_bfloat16* __restrict__ Bh1, const __nv_bfloat16* __restrict__ Bl1,
    float* __restrict__ C1)
{
    const int z = blockIdx.z;
    const __nv_bfloat16* BhP = (z == 0) ? Bh0 : Bh1;
    const __nv_bfloat16* BlP = (z == 0) ? Bl0 : Bl1;
    float* C = (z == 0) ? C0 : C1;

    __shared__ __nv_bfloat16 sA[2][GBM * LDS_W];
    __shared__ __nv_bfloat16 sB[2][GBN * LDS_W];

    const int tid = threadIdx.x;
    const int lane = tid & 31;
    const int wid = tid >> 5;
    const int wm = (wid & 3) * 32;
    const int wn = (wid >> 2) * 64;
    const int g = lane >> 2;
    const int t = lane & 3;
    const int lrow = lane & 15;
    const int lsel = (lane >> 4) * 8;

    const int bm = blockIdx.y * GBM;
    const int bn = blockIdx.x * GBN;

    const int grow = tid >> 1;
    const int gcol = (tid & 1) * 16;

    const uint32_t sAu = (uint32_t)__cvta_generic_to_shared(&sA[0][0]);
    const uint32_t sBu = (uint32_t)__cvta_generic_to_shared(&sB[0][0]);

    float acc[2][8][4];
#pragma unroll
    for (int i = 0; i < 2; i++)
#pragma unroll
        for (int j = 0; j < 8; j++)
#pragma unroll
            for (int r = 0; r < 4; r++) acc[i][j][r] = 0.f;

    auto fetch = [&](int c, uint4& ra0, uint4& ra1, uint4& rb0, uint4& rb1) {
        const int pass = c >> 6;
        const int k0 = (c & 63) * GBK;
        const __nv_bfloat16* Ap = (pass == 2) ? Al : Ah;
        const __nv_bfloat16* Bp = (pass == 1) ? BlP : BhP;
        const size_t ga = (size_t)(bm + grow) * KDIM + k0 + gcol;
        const size_t gb = (size_t)(bn + grow) * KDIM + k0 + gcol;
        ra0 = *(const uint4*)(Ap + ga);
        ra1 = *(const uint4*)(Ap + ga + 8);
        rb0 = *(const uint4*)(Bp + gb);
        rb1 = *(const uint4*)(Bp + gb + 8);
    };
    auto store = [&](int buf, const uint4& ra0, const uint4& ra1,
                     const uint4& rb0, const uint4& rb1) {
        __nv_bfloat16* pa = &sA[buf][grow * LDS_W + gcol];
        __nv_bfloat16* pb = &sB[buf][grow * LDS_W + gcol];
        *(uint4*)pa = ra0;
        *(uint4*)(pa + 8) = ra1;
        *(uint4*)pb = rb0;
        *(uint4*)(pb + 8) = rb1;
    };

    {
        uint4 ra0, ra1, rb0, rb1;
        fetch(0, ra0, ra1, rb0, rb1);
        store(0, ra0, ra1, rb0, rb1);
    }
    __syncthreads();

    for (int c = 0; c < NCHUNK; c++) {
        const int buf = c & 1;
        const bool more = (c + 1 < NCHUNK);
        uint4 ra0, ra1, rb0, rb1;
        if (more) fetch(c + 1, ra0, ra1, rb0, rb1);

        const uint32_t sa = sAu + (uint32_t)buf * TILE_B2;
        const uint32_t sb = sBu + (uint32_t)buf * TILE_B2;
#pragma unroll
        for (int kk = 0; kk < GBK; kk += 16) {
            uint32_t af[2][4];
#pragma unroll
            for (int mt = 0; mt < 2; mt++) {
                const uint32_t ra = sa + (uint32_t)((wm + mt * 16 + lrow) * LDS_W + kk + lsel) * 2;
                LDSM4(af[mt][0], af[mt][1], af[mt][2], af[mt][3], ra);
            }
            uint32_t bfr[8][2];
#pragma unroll
            for (int p = 0; p < 4; p++) {
                const uint32_t rb = sb + (uint32_t)((wn + p * 16 + lrow) * LDS_W + kk + lsel) * 2;
                uint32_t r0, r1, r2, r3;
                LDSM4(r0, r1, r2, r3, rb);
                bfr[2 * p][0] = r0; bfr[2 * p + 1][0] = r1;
                bfr[2 * p][1] = r2; bfr[2 * p + 1][1] = r3;
            }
#pragma unroll
            for (int mt = 0; mt < 2; mt++)
#pragma unroll
                for (int nt = 0; nt < 8; nt++)
                    mma16816(acc[mt][nt], af[mt], bfr[nt]);
        }

        if (more) store(buf ^ 1, ra0, ra1, rb0, rb1);
        __syncthreads();
    }

#pragma unroll
    for (int mt = 0; mt < 2; mt++) {
        const int r0 = bm + wm + mt * 16 + g;
#pragma unroll
        for (int nt = 0; nt < 8; nt++) {
            const int col = bn + wn + nt * 8 + 2 * t;
            *(float2*)&C[(size_t)r0 * HIDDEN + col] = make_float2(acc[mt][nt][0], acc[mt][nt][1]);
            *(float2*)&C[(size_t)(r0 + 8) * HIDDEN + col] = make_float2(acc[mt][nt][2], acc[mt][nt][3]);
        }
    }
}

// ---------------------------------------------------------------------------
// fp16 2-pass GEMM: C = (Ah + Al) @ Bh^T   (A fully split fp16, B single fp16)
// ---------------------------------------------------------------------------
__global__ __launch_bounds__(256) void gemm2h_kernel(
    const __half* __restrict__ Ah, const __half* __restrict__ Al,
    const __half* __restrict__ Bh, float* __restrict__ C)
{
    __shared__ __half sA[2][GBM * LDS_W];
    __shared__ __half sB[2][GBN * LDS_W];

    const int tid = threadIdx.x;
    const int lane = tid & 31;
    const int wid = tid >> 5;
    const int wm = (wid & 3) * 32;
    const int wn = (wid >> 2) * 64;
    const int g = lane >> 2;
    const int t = lane & 3;
    const int lrow = lane & 15;
    const int lsel = (lane >> 4) * 8;

    const int bm = blockIdx.y * GBM;
    const int bn = blockIdx.x * GBN;

    const int grow = tid >> 1;
    const int gcol = (tid & 1) * 16;

    const uint32_t sAu = (uint32_t)__cvta_generic_to_shared(&sA[0][0]);
    const uint32_t sBu = (uint32_t)__cvta_generic_to_shared(&sB[0][0]);

    float acc[2][8][4];
#pragma unroll
    for (int i = 0; i < 2; i++)
#pragma unroll
        for (int j = 0; j < 8; j++)
#pragma unroll
            for (int r = 0; r < 4; r++) acc[i][j][r] = 0.f;

    auto fetch = [&](int c, uint4& ra0, uint4& ra1, uint4& rb0, uint4& rb1) {
        const int pass = c >> 6;
        const int k0 = (c & 63) * GBK;
        const __half* Ap = pass ? Al : Ah;
        const size_t ga = (size_t)(bm + grow) * KDIM + k0 + gcol;
        const size_t gb = (size_t)(bn + grow) * KDIM + k0 + gcol;
        ra0 = *(const uint4*)(Ap + ga);
        ra1 = *(const uint4*)(Ap + ga + 8);
        rb0 = *(const uint4*)(Bh + gb);
        rb1 = *(const uint4*)(Bh + gb + 8);
    };
    auto store = [&](int buf, const uint4& ra0, const uint4& ra1,
                     const uint4& rb0, const uint4& rb1) {
        __half* pa = &sA[buf][grow * LDS_W + gcol];
        __half* pb = &sB[buf][grow * LDS_W + gcol];
        *(uint4*)pa = ra0;
        *(uint4*)(pa + 8) = ra1;
        *(uint4*)pb = rb0;
        *(uint4*)(pb + 8) = rb1;
    };

    {
        uint4 ra0, ra1, rb0, rb1;
        fetch(0, ra0, ra1, rb0, rb1);
        store(0, ra0, ra1, rb0, rb1);
    }
    __syncthreads();

    for (int c = 0; c < NCHUNK2; c++) {
        const int buf = c & 1;
        const bool more = (c + 1 < NCHUNK2);
        uint4 ra0, ra1, rb0, rb1;
        if (more) fetch(c + 1, ra0, ra1, rb0, rb1);

        const uint32_t sa = sAu + (uint32_t)buf * TILE_B2;
        const uint32_t sb = sBu + (uint32_t)buf * TILE_B2;
#pragma unroll
        for (int kk = 0; kk < GBK; kk += 16) {
            uint32_t af[2][4];
#pragma unroll
            for (int mt = 0; mt < 2; mt++) {
                const uint32_t ra = sa + (uint32_t)((wm + mt * 16 + lrow) * LDS_W + kk + lsel) * 2;
                LDSM4(af[mt][0], af[mt][1], af[mt][2], af[mt][3], ra);
            }
            uint32_t bfr[8][2];
#pragma unroll
            for (int p = 0; p < 4; p++) {
                const uint32_t rb = sb + (uint32_t)((wn + p * 16 + lrow) * LDS_W + kk + lsel) * 2;
                uint32_t r0, r1, r2, r3;
                LDSM4(r0, r1, r2, r3, rb);
                bfr[2 * p][0] = r0; bfr[2 * p + 1][0] = r1;
                bfr[2 * p][1] = r2; bfr[2 * p + 1][1] = r3;
            }
#pragma unroll
            for (int mt = 0; mt < 2; mt++)
#pragma unroll
                for (int nt = 0; nt < 8; nt++)
                    mma16816h(acc[mt][nt], af[mt], bfr[nt]);
        }

        if (more) store(buf ^ 1, ra0, ra1, rb0, rb1);
        __syncthreads();
    }

#pragma unroll
    for (int mt = 0; mt < 2; mt++) {
        const int r0 = bm + wm + mt * 16 + g;
#pragma unroll
        for (int nt = 0; nt < 8; nt++) {
            const int col = bn + wn + nt * 8 + 2 * t;
            *(float2*)&C[(size_t)r0 * HIDDEN + col] = make_float2(acc[mt][nt][0], acc[mt][nt][1]);
            *(float2*)&C[(size_t)(r0 + 8) * HIDDEN + col] = make_float2(acc[mt][nt][2], acc[mt][nt][3]);
        }
    }
}

// ---------------------------------------------------------------------------
// RoPE + split to bf16 hi/lo for Q and K.
// ---------------------------------------------------------------------------
__global__ void rope_split_kernel(const float* __restrict__ q, const float* __restrict__ k,
                                  __nv_bfloat16* __restrict__ qh, __nv_bfloat16* __restrict__ ql,
                                  __nv_bfloat16* __restrict__ kh, __nv_bfloat16* __restrict__ kl)
{
    int idx = blockIdx.x * blockDim.x + threadIdx.x;
    int d = idx & 63;
    int m = idx >> 10;
    int l = m & (SEQL - 1);
    int h = (idx >> 6) & (HEADS - 1);

    float e = (2.0f * (float)d) / 128.0f;
    float inv = 1.0f / powf(10000.0f, e);
    float ang = (float)l * inv;
    float s, c;
    sincosf(ang, &s, &c);

    size_t base = (size_t)m * HIDDEN + h * HD + d;
    float q1 = q[base], q2 = q[base + 64];
    float k1 = k[base], k2 = k[base + 64];
    float qa = q1 * c - q2 * s;
    float qb = q2 * c + q1 * s;
    float ka = k1 * c - k2 * s;
    float kb = k2 * c + k1 * s;

    __nv_bfloat16 t0;
    t0 = __float2bfloat16(qa); qh[base] = t0;      ql[base] = __float2bfloat16(qa - __bfloat162float(t0));
    t0 = __float2bfloat16(qb); qh[base + 64] = t0; ql[base + 64] = __float2bfloat16(qb - __bfloat162float(t0));
    t0 = __float2bfloat16(ka); kh[base] = t0;      kl[base] = __float2bfloat16(ka - __bfloat162float(t0));
    t0 = __float2bfloat16(kb); kh[base + 64] = t0; kl[base + 64] = __float2bfloat16(kb - __bfloat162float(t0));
}

// ---------------------------------------------------------------------------
// V transpose + round to single fp16
// ---------------------------------------------------------------------------
__global__ __launch_bounds__(256) void vt_half_kernel(
    const float* __restrict__ v, __half* __restrict__ vt)
{
    __shared__ float tile[32][33];
    const int bh = blockIdx.z;
    const int b = bh >> 4, h = bh & 15;
    const int l0 = blockIdx.x * 32, d0 = blockIdx.y * 32;
    const int tx = threadIdx.x, ty = threadIdx.y;

#pragma unroll
    for (int i = 0; i < 4; i++) {
        int r = ty + i * 8;
        tile[r][tx] = v[(size_t)(b * SEQL + l0 + r) * HIDDEN + h * HD + d0 + tx];
    }
    __syncthreads();
#pragma unroll
    for (int i = 0; i < 4; i++) {
        int r = ty + i * 8;
        size_t o = ((size_t)((b * HEADS + h) * HD + d0 + r)) * SEQL + l0 + tx;
        vt[o] = __float2half_rn(tile[tx][r]);
    }
}

// ---------------------------------------------------------------------------
// Flash attention: S = 3-term bf16 (unchanged); PV = 2-term fp16.
// ---------------------------------------------------------------------------
#define QW 136
#define VW 72
#define OQH 0
#define OQL 17408
#define OKH 34816
#define OKL 43520
#define OVH 52224
#define FLASH_SMEM ((52224 + 128 * VW) * 2) // 122880 bytes

__device__ __forceinline__ void pack_pair(float a, float b, uint32_t& hi_pack, uint32_t& lo_pack)
{
    // fp16 hi/lo split, a in low half, b in high half
    __half2 h = __floats2half2_rn(a, b);
    hi_pack = *reinterpret_cast<uint32_t*>(&h);
    float ra = a - __half2float(__low2half(h));
    float rb = b - __half2float(__high2half(h));
    __half2 l = __floats2half2_rn(ra, rb);
    lo_pack = *reinterpret_cast<uint32_t*>(&l);
}

__global__ __launch_bounds__(256) void flash_mma_kernel(
    const __nv_bfloat16* __restrict__ Qh, const __nv_bfloat16* __restrict__ Ql,
    const __nv_bfloat16* __restrict__ Kh, const __nv_bfloat16* __restrict__ Kl,
    const __half* __restrict__ Vt16,
    float* __restrict__ O)
{
    extern __shared__ __nv_bfloat16 fs[];
    __nv_bfloat16* sQh = fs + OQH;
    __nv_bfloat16* sQl = fs + OQL;
    __nv_bfloat16* sKh = fs + OKH;
    __nv_bfloat16* sKl = fs + OKL;
    __half* sV = (__half*)(fs + OVH);

    const uint32_t fsU = (uint32_t)__cvta_generic_to_shared(fs);
    const uint32_t sQhU = fsU + OQH * 2;
    const uint32_t sQlU = fsU + OQL * 2;
    const uint32_t sKhU = fsU + OKH * 2;
    const uint32_t sKlU = fsU + OKL * 2;
    const uint32_t sVU = fsU + OVH * 2;

    const int qt = blockIdx.x, h = blockIdx.y, b = blockIdx.z;
    const int tid = threadIdx.x, lane = tid & 31, wid = tid >> 5;
    const int g = lane >> 2, t = lane & 3;
    const int lrow = lane & 15;
    const int lsel = (lane >> 4) * 8;
    const int wm = wid * 16;
    const float scale = 0.0883883476483184f;

    {
        const size_t base = (size_t)(b * SEQL + qt * 128) * HIDDEN + h * HD;
#pragma unroll
        for (int it = 0; it < 8; it++) {
            int id = tid + it * 256;
            int r = id >> 4, c8 = (id & 15) * 8;
            *(uint4*)&sQh[r * QW + c8] = *(const uint4*)&Qh[base + (size_t)r * HIDDEN + c8];
            *(uint4*)&sQl[r * QW + c8] = *(const uint4*)&Ql[base + (size_t)r * HIDDEN + c8];
        }
    }

    float m0 = -1e30f, m1 = -1e30f, l0 = 0.f, l1 = 0.f;
    float oacc[16][4];
#pragma unroll
    for (int nt = 0; nt < 16; nt++)
#pragma unroll
        for (int r = 0; r < 4; r++) oacc[nt][r] = 0.f;

    const int nkt = 2 * qt + 2;
    for (int kt = 0; kt < nkt; kt++) {
        __syncthreads();
#pragma unroll
        for (int it = 0; it < 4; it++) {
            int id = tid + it * 256;
            int r = id >> 4, c8 = (id & 15) * 8;
            size_t gk = (size_t)(b * SEQL + kt * 64 + r) * HIDDEN + h * HD + c8;
            *(uint4*)&sKh[r * QW + c8] = *(const uint4*)&Kh[gk];
            *(uint4*)&sKl[r * QW + c8] = *(const uint4*)&Kl[gk];
            int rv = id >> 3, cv = (id & 7) * 8;
            size_t gv = (size_t)((b * HEADS + h) * HD + rv) * SEQL + kt * 64 + cv;
            *(uint4*)&sV[rv * VW + cv] = *(const uint4*)&Vt16[gv];
        }
        __syncthreads();

        float sacc[8][4];
#pragma unroll
        for (int nt = 0; nt < 8; nt++)
#pragma unroll
            for (int r = 0; r < 4; r++) sacc[nt][r] = 0.f;

#pragma unroll
        for (int kc = 0; kc < 8; kc++) {
            const int kk = kc * 16;
            uint32_t aqh[4], aql[4];
            const uint32_t aoff = (uint32_t)((wm + lrow) * QW + kk + lsel) * 2;
            LDSM4(aqh[0], aqh[1], aqh[2], aqh[3], sQhU + aoff);
            LDSM4(aql[0], aql[1], aql[2], aql[3], sQlU + aoff);
            uint32_t bh[8][2], bl[8][2];
#pragma unroll
            for (int p = 0; p < 4; p++) {
                const uint32_t boff = (uint32_t)((p * 16 + lrow) * QW + kk + lsel) * 2;
                uint32_t r0, r1, r2, r3;
                LDSM4(r0, r1, r2, r3, sKhU + boff);
                bh[2 * p][0] = r0; bh[2 * p + 1][0] = r1;
                bh[2 * p][1] = r2; bh[2 * p + 1][1] = r3;
                LDSM4(r0, r1, r2, r3, sKlU + boff);
                bl[2 * p][0] = r0; bl[2 * p + 1][0] = r1;
                bl[2 * p][1] = r2; bl[2 * p + 1][1] = r3;
            }
#pragma unroll
            for (int nt = 0; nt < 8; nt++) {
                mma16816(sacc[nt], aqh, bh[nt]);
                mma16816(sacc[nt], aqh, bl[nt]);
                mma16816(sacc[nt], aql, bh[nt]);
            }
        }

        const int row0 = qt * 128 + wm + g;
        const int row1 = row0 + 8;
#pragma unroll
        for (int nt = 0; nt < 8; nt++) {
            sacc[nt][0] *= scale; sacc[nt][1] *= scale;
            sacc[nt][2] *= scale; sacc[nt][3] *= scale;
        }
        if (kt * 64 + 63 > qt * 128 + wm) {
#pragma unroll
            for (int nt = 0; nt < 8; nt++) {
                const int col = kt * 64 + nt * 8 + 2 * t;
                if (col > row0)     sacc[nt][0] = -1e30f;
                if (col + 1 > row0) sacc[nt][1] = -1e30f;
                if (col > row1)     sacc[nt][2] = -1e30f;
                if (col + 1 > row1) sacc[nt][3] = -1e30f;
            }
        }

        float mt0 = -1e30f, mt1 = -1e30f;
#pragma unroll
        for (int nt = 0; nt < 8; nt++) {
            mt0 = fmaxf(mt0, fmaxf(sacc[nt][0], sacc[nt][1]));
            mt1 = fmaxf(mt1, fmaxf(sacc[nt][2], sacc[nt][3]));
        }
        mt0 = fmaxf(mt0, __shfl_xor_sync(0xffffffffu, mt0, 1));
        mt0 = fmaxf(mt0, __shfl_xor_sync(0xffffffffu, mt0, 2));
        mt1 = fmaxf(mt1, __shfl_xor_sync(0xffffffffu, mt1, 1));
        mt1 = fmaxf(mt1, __shfl_xor_sync(0xffffffffu, mt1, 2));

        const float nm0 = fmaxf(m0, mt0), nm1 = fmaxf(m1, mt1);
        const float alpha0 = __expf(m0 - nm0), alpha1 = __expf(m1 - nm1);
        float ps0 = 0.f, ps1 = 0.f;
#pragma unroll
        for (int nt = 0; nt < 8; nt++) {
            sacc[nt][0] = __expf(sacc[nt][0] - nm0);
            sacc[nt][1] = __expf(sacc[nt][1] - nm0);
            sacc[nt][2] = __expf(sacc[nt][2] - nm1);
            sacc[nt][3] = __expf(sacc[nt][3] - nm1);
            ps0 += sacc[nt][0] + sacc[nt][1];
            ps1 += sacc[nt][2] + sacc[nt][3];
        }
        ps0 += __shfl_xor_sync(0xffffffffu, ps0, 1);
        ps0 += __shfl_xor_sync(0xffffffffu, ps0, 2);
        ps1 += __shfl_xor_sync(0xffffffffu, ps1, 1);
        ps1 += __shfl_xor_sync(0xffffffffu, ps1, 2);
        l0 = alpha0 * l0 + ps0; m0 = nm0;
        l1 = alpha1 * l1 + ps1; m1 = nm1;
#pragma unroll
        for (int nt = 0; nt < 16; nt++) {
            oacc[nt][0] *= alpha0; oacc[nt][1] *= alpha0;
            oacc[nt][2] *= alpha1; oacc[nt][3] *= alpha1;
        }

        // P -> fp16 hi/lo fragments
        uint32_t ph[4][4], pl[4][4];
#pragma unroll
        for (int kc = 0; kc < 4; kc++) {
            const int j0 = 2 * kc, j1 = 2 * kc + 1;
            pack_pair(sacc[j0][0], sacc[j0][1], ph[kc][0], pl[kc][0]);
            pack_pair(sacc[j0][2], sacc[j0][3], ph[kc][1], pl[kc][1]);
            pack_pair(sacc[j1][0], sacc[j1][1], ph[kc][2], pl[kc][2]);
            pack_pair(sacc[j1][2], sacc[j1][3], ph[kc][3], pl[kc][3]);
        }

        // O += (Ph + Pl) * V   (fp16, 2 terms)
#pragma unroll
        for (int kc = 0; kc < 4; kc++) {
#pragma unroll
            for (int p = 0; p < 8; p++) {
                const uint32_t voff = (uint32_t)((p * 16 + lrow) * VW + kc * 16 + lsel) * 2;
                uint32_t r0, r1, r2, r3;
                LDSM4(r0, r1, r2, r3, sVU + voff);
                uint32_t v0[2] = { r0, r2 };
                uint32_t v1[2] = { r1, r3 };
                mma16816h(oacc[2 * p], ph[kc], v0);
                mma16816h(oacc[2 * p], pl[kc], v0);
                mma16816h(oacc[2 * p + 1], ph[kc], v1);
                mma16816h(oacc[2 * p + 1], pl[kc], v1);
            }
        }
    }

    const float i0 = 1.0f / l0, i1 = 1.0f / l1;
    const size_t rbase = (size_t)(b * SEQL + qt * 128 + wm + g) * HIDDEN + h * HD + 2 * t;
#pragma unroll
    for (int nt = 0; nt < 16; nt++) {
        *(float2*)&O[rbase + nt * 8] = make_float2(oacc[nt][0] * i0, oacc[nt][1] * i0);
        *(float2*)&O[rbase + 8 * HIDDEN + nt * 8] = make_float2(oacc[nt][2] * i1, oacc[nt][3] * i1);
    }
}

// ---------------------------------------------------------------------------
extern "C" void kernel_launch(void* const* d_in, const int* in_sizes, int n_in,
                              void* d_out, int out_size)
{
    const float* x  = (const float*)d_in[0];
    const float* wq = (const float*)d_in[1];
    const float* wk = (const float*)d_in[2];
    const float* wv = (const float*)d_in[3];
    const float* wo = (const float*)d_in[4];
    float* out = (float*)d_out;

    float *q, *k, *v, *o;
    cudaGetSymbolAddress((void**)&q, g_q);
    cudaGetSymbolAddress((void**)&k, g_k);
    cudaGetSymbolAddress((void**)&v, g_v);
    cudaGetSymbolAddress((void**)&o, g_o);

    __nv_bfloat16 *xh, *xl, *wqh, *wql, *wkh, *wkl;
    __nv_bfloat16 *qh, *ql, *kh, *kl;
    __half *xh16, *xl16, *oh16, *ol16, *wvh16, *woh16, *vt16;
    cudaGetSymbolAddress((void**)&xh, g_xh);
    cudaGetSymbolAddress((void**)&xl, g_xl);
    cudaGetSymbolAddress((void**)&wqh, g_wqh);
    cudaGetSymbolAddress((void**)&wql, g_wql);
    cudaGetSymbolAddress((void**)&wkh, g_wkh);
    cudaGetSymbolAddress((void**)&wkl, g_wkl);
    cudaGetSymbolAddress((void**)&qh, g_qh);
    cudaGetSymbolAddress((void**)&ql, g_ql);
    cudaGetSymbolAddress((void**)&kh, g_kh);
    cudaGetSymbolAddress((void**)&kl, g_kl);
    cudaGetSymbolAddress((void**)&xh16, g_xh16);
    cudaGetSymbolAddress((void**)&xl16, g_xl16);
    cudaGetSymbolAddress((void**)&oh16, g_oh16);
    cudaGetSymbolAddress((void**)&ol16, g_ol16);
    cudaGetSymbolAddress((void**)&wvh16, g_wvh16);
    cudaGetSymbolAddress((void**)&woh16, g_woh16);
    cudaGetSymbolAddress((void**)&vt16, g_vt16);

    const int nx4 = MROWS * HIDDEN / 4;
    const int nw4 = HIDDEN * HIDDEN / 4;
    split_kernel<<<(nx4 + 255) / 256, 256>>>((const float4*)x, xh, xl, nx4);
    split2h_kernel<<<(nx4 + 255) / 256, 256>>>((const float4*)x, xh16, xl16, nx4);
    split_kernel<<<(nw4 + 255) / 256, 256>>>((const float4*)wq, wqh, wql, nw4);
    split_kernel<<<(nw4 + 255) / 256, 256>>>((const float4*)wk, wkh, wkl, nw4);
    round_h_kernel<<<(nw4 + 255) / 256, 256>>>((const float4*)wv, wvh16, nw4);
    round_h_kernel<<<(nw4 + 255) / 256, 256>>>((const float4*)wo, woh16, nw4);

    dim3 gg(HIDDEN / GBN, MROWS / GBM); // (16, 32)
    // Q,K: one launch (grid.z = 2), bf16 3-pass
    gemm3_kernel<<<dim3(gg.x, gg.y, 2), 256>>>(xh, xl, wqh, wql, q, wkh, wkl, k);
    // V: fp16 2-pass
    gemm2h_kernel<<<gg, 256>>>(xh16, xl16, wvh16, v);

    rope_split_kernel<<<(MROWS * HEADS * 64) / 256, 256>>>(q, k, qh, ql, kh, kl);
    vt_half_kernel<<<dim3(SEQL / 32, HD / 32, NBATCH * HEADS), dim3(32, 8)>>>(v, vt16);

    cudaFuncSetAttribute(flash_mma_kernel, cudaFuncAttributeMaxDynamicSharedMemorySize, FLASH_SMEM);
    flash_mma_kernel<<<dim3(SEQL / 128, HEADS, NBATCH), 256, FLASH_SMEM>>>(
        qh, ql, kh, kl, vt16, o);

    split2h_kernel<<<(nx4 + 255) / 256, 256>>>((const float4*)o, oh16, ol16, nx4);
    // O-projection: fp16 2-pass
    gemm2h_kernel<<<gg, 256>>>(oh16, ol16, woh16, out);
}

// round 14
// speedup vs baseline: 1.9169x; 1.1766x over previous
#include <cuda_runtime.h>
#include <cuda_bf16.h>
#include <cuda_fp16.h>
#include <math.h>
#include <stdint.h>

#define HIDDEN 2048
#define HEADS 16
#define HD 128
#define SEQL 2048
#define NBATCH 2
#define MROWS (NBATCH * SEQL) // 4096
#define KDIM 2048

// ---------------------------------------------------------------------------
// Scratch: __device__ globals (no cudaMalloc allowed)
// ---------------------------------------------------------------------------
__device__ float g_q[(size_t)MROWS * HIDDEN];
__device__ float g_k[(size_t)MROWS * HIDDEN];
__device__ float g_v[(size_t)MROWS * HIDDEN];
__device__ float g_o[(size_t)MROWS * HIDDEN];

// fp16 2-term operands (all projections)
__device__ __half g_xh16[(size_t)MROWS * HIDDEN];
__device__ __half g_xl16[(size_t)MROWS * HIDDEN];
__device__ __half g_oh16[(size_t)MROWS * HIDDEN];
__device__ __half g_ol16[(size_t)MROWS * HIDDEN];
__device__ __half g_wqh16[(size_t)HIDDEN * HIDDEN];
__device__ __half g_wkh16[(size_t)HIDDEN * HIDDEN];
__device__ __half g_wvh16[(size_t)HIDDEN * HIDDEN];
__device__ __half g_woh16[(size_t)HIDDEN * HIDDEN];

// bf16 split Q/K (post-RoPE) and fp16 transposed V for flash
__device__ __nv_bfloat16 g_qh[(size_t)MROWS * HIDDEN];
__device__ __nv_bfloat16 g_ql[(size_t)MROWS * HIDDEN];
__device__ __nv_bfloat16 g_kh[(size_t)MROWS * HIDDEN];
__device__ __nv_bfloat16 g_kl[(size_t)MROWS * HIDDEN];
__device__ __half g_vt16[(size_t)MROWS * HIDDEN];

// ---------------------------------------------------------------------------
__device__ __forceinline__ void mma16816(float* c, const uint32_t* a, const uint32_t* b)
{
    asm volatile(
        "mma.sync.aligned.m16n8k16.row.col.f32.bf16.bf16.f32 "
        "{%0,%1,%2,%3}, {%4,%5,%6,%7}, {%8,%9}, {%0,%1,%2,%3};"
        : "+f"(c[0]), "+f"(c[1]), "+f"(c[2]), "+f"(c[3])
        : "r"(a[0]), "r"(a[1]), "r"(a[2]), "r"(a[3]), "r"(b[0]), "r"(b[1]));
}

__device__ __forceinline__ void mma16816h(float* c, const uint32_t* a, const uint32_t* b)
{
    asm volatile(
        "mma.sync.aligned.m16n8k16.row.col.f32.f16.f16.f32 "
        "{%0,%1,%2,%3}, {%4,%5,%6,%7}, {%8,%9}, {%0,%1,%2,%3};"
        : "+f"(c[0]), "+f"(c[1]), "+f"(c[2]), "+f"(c[3])
        : "r"(a[0]), "r"(a[1]), "r"(a[2]), "r"(a[3]), "r"(b[0]), "r"(b[1]));
}

#define LDSM4(r0, r1, r2, r3, addr) \
    asm volatile("ldmatrix.sync.aligned.m8n8.x4.shared.b16 {%0,%1,%2,%3}, [%4];" \
                 : "=r"(r0), "=r"(r1), "=r"(r2), "=r"(r3) : "r"(addr))

// ---------------------------------------------------------------------------
// Split fp32 -> (fp16 hi, fp16 lo)
// ---------------------------------------------------------------------------
__global__ void split2h_kernel(const float4* __restrict__ a,
                               __half* __restrict__ hi,
                               __half* __restrict__ lo, int n4)
{
    int i = blockIdx.x * blockDim.x + threadIdx.x;
    if (i >= n4) return;
    float4 v = a[i];
    __half h0 = __float2half_rn(v.x);
    __half h1 = __float2half_rn(v.y);
    __half h2 = __float2half_rn(v.z);
    __half h3 = __float2half_rn(v.w);
    ushort4 hv, lv;
    hv.x = __half_as_ushort(h0); hv.y = __half_as_ushort(h1);
    hv.z = __half_as_ushort(h2); hv.w = __half_as_ushort(h3);
    lv.x = __half_as_ushort(__float2half_rn(v.x - __half2float(h0)));
    lv.y = __half_as_ushort(__float2half_rn(v.y - __half2float(h1)));
    lv.z = __half_as_ushort(__float2half_rn(v.z - __half2float(h2)));
    lv.w = __half_as_ushort(__float2half_rn(v.w - __half2float(h3)));
    *(ushort4*)(hi + (size_t)i * 4) = hv;
    *(ushort4*)(lo + (size_t)i * 4) = lv;
}

// Round fp32 -> fp16 only
__global__ void round_h_kernel(const float4* __restrict__ a,
                               __half* __restrict__ hi, int n4)
{
    int i = blockIdx.x * blockDim.x + threadIdx.x;
    if (i >= n4) return;
    float4 v = a[i];
    ushort4 hv;
    hv.x = __half_as_ushort(__float2half_rn(v.x));
    hv.y = __half_as_ushort(__float2half_rn(v.y));
    hv.z = __half_as_ushort(__float2half_rn(v.z));
    hv.w = __half_as_ushort(__float2half_rn(v.w));
    *(ushort4*)(hi + (size_t)i * 4) = hv;
}

// ---------------------------------------------------------------------------
// fp16 2-pass GEMM: C = (Ah + Al) @ Bh^T.  grid.z selects among up to 3
// (B, C) sets sharing the same A (QKV in one launch).
// ---------------------------------------------------------------------------
#define GBM 128
#define GBN 128
#define GBK 32
#define LDS_W 40
#define TILE_B2 (GBM * LDS_W * 2)   // bytes per buffer = 10240
#define NCHUNK2 (2 * KDIM / GBK)    // 128

__global__ __launch_bounds__(256) void gemm2h_kernel(
    const __half* __restrict__ Ah, const __half* __restrict__ Al,
    const __half* __restrict__ Bh0, float* __restrict__ C0,
    const __half* __restrict__ Bh1, float* __restrict__ C1,
    const __half* __restrict__ Bh2, float* __restrict__ C2)
{
    const int z = blockIdx.z;
    const __half* Bh = (z == 0) ? Bh0 : (z == 1) ? Bh1 : Bh2;
    float* C = (z == 0) ? C0 : (z == 1) ? C1 : C2;

    __shared__ __half sA[2][GBM * LDS_W];
    __shared__ __half sB[2][GBN * LDS_W];

    const int tid = threadIdx.x;
    const int lane = tid & 31;
    const int wid = tid >> 5;
    const int wm = (wid & 3) * 32;
    const int wn = (wid >> 2) * 64;
    const int g = lane >> 2;
    const int t = lane & 3;
    const int lrow = lane & 15;
    const int lsel = (lane >> 4) * 8;

    const int bm = blockIdx.y * GBM;
    const int bn = blockIdx.x * GBN;

    const int grow = tid >> 1;
    const int gcol = (tid & 1) * 16;

    const uint32_t sAu = (uint32_t)__cvta_generic_to_shared(&sA[0][0]);
    const uint32_t sBu = (uint32_t)__cvta_generic_to_shared(&sB[0][0]);

    float acc[2][8][4];
#pragma unroll
    for (int i = 0; i < 2; i++)
#pragma unroll
        for (int j = 0; j < 8; j++)
#pragma unroll
            for (int r = 0; r < 4; r++) acc[i][j][r] = 0.f;

    auto fetch = [&](int c, uint4& ra0, uint4& ra1, uint4& rb0, uint4& rb1) {
        const int pass = c >> 6;
        const int k0 = (c & 63) * GBK;
        const __half* Ap = pass ? Al : Ah;
        const size_t ga = (size_t)(bm + grow) * KDIM + k0 + gcol;
        const size_t gb = (size_t)(bn + grow) * KDIM + k0 + gcol;
        ra0 = *(const uint4*)(Ap + ga);
        ra1 = *(const uint4*)(Ap + ga + 8);
        rb0 = *(const uint4*)(Bh + gb);
        rb1 = *(const uint4*)(Bh + gb + 8);
    };
    auto store = [&](int buf, const uint4& ra0, const uint4& ra1,
                     const uint4& rb0, const uint4& rb1) {
        __half* pa = &sA[buf][grow * LDS_W + gcol];
        __half* pb = &sB[buf][grow * LDS_W + gcol];
        *(uint4*)pa = ra0;
        *(uint4*)(pa + 8) = ra1;
        *(uint4*)pb = rb0;
        *(uint4*)(pb + 8) = rb1;
    };

    {
        uint4 ra0, ra1, rb0, rb1;
        fetch(0, ra0, ra1, rb0, rb1);
        store(0, ra0, ra1, rb0, rb1);
    }
    __syncthreads();

    for (int c = 0; c < NCHUNK2; c++) {
        const int buf = c & 1;
        const bool more = (c + 1 < NCHUNK2);
        uint4 ra0, ra1, rb0, rb1;
        if (more) fetch(c + 1, ra0, ra1, rb0, rb1);

        const uint32_t sa = sAu + (uint32_t)buf * TILE_B2;
        const uint32_t sb = sBu + (uint32_t)buf * TILE_B2;
#pragma unroll
        for (int kk = 0; kk < GBK; kk += 16) {
            uint32_t af[2][4];
#pragma unroll
            for (int mt = 0; mt < 2; mt++) {
                const uint32_t ra = sa + (uint32_t)((wm + mt * 16 + lrow) * LDS_W + kk + lsel) * 2;
                LDSM4(af[mt][0], af[mt][1], af[mt][2], af[mt][3], ra);
            }
            uint32_t bfr[8][2];
#pragma unroll
            for (int p = 0; p < 4; p++) {
                const uint32_t rb = sb + (uint32_t)((wn + p * 16 + lrow) * LDS_W + kk + lsel) * 2;
                uint32_t r0, r1, r2, r3;
                LDSM4(r0, r1, r2, r3, rb);
                bfr[2 * p][0] = r0; bfr[2 * p + 1][0] = r1;
                bfr[2 * p][1] = r2; bfr[2 * p + 1][1] = r3;
            }
#pragma unroll
            for (int mt = 0; mt < 2; mt++)
#pragma unroll
                for (int nt = 0; nt < 8; nt++)
                    mma16816h(acc[mt][nt], af[mt], bfr[nt]);
        }

        if (more) store(buf ^ 1, ra0, ra1, rb0, rb1);
        __syncthreads();
    }

#pragma unroll
    for (int mt = 0; mt < 2; mt++) {
        const int r0 = bm + wm + mt * 16 + g;
#pragma unroll
        for (int nt = 0; nt < 8; nt++) {
            const int col = bn + wn + nt * 8 + 2 * t;
            *(float2*)&C[(size_t)r0 * HIDDEN + col] = make_float2(acc[mt][nt][0], acc[mt][nt][1]);
            *(float2*)&C[(size_t)(r0 + 8) * HIDDEN + col] = make_float2(acc[mt][nt][2], acc[mt][nt][3]);
        }
    }
}

// ---------------------------------------------------------------------------
// RoPE + split to bf16 hi/lo for Q and K (flash softmax path stays bf16 x3).
// ---------------------------------------------------------------------------
__global__ void rope_split_kernel(const float* __restrict__ q, const float* __restrict__ k,
                                  __nv_bfloat16* __restrict__ qh, __nv_bfloat16* __restrict__ ql,
                                  __nv_bfloat16* __restrict__ kh, __nv_bfloat16* __restrict__ kl)
{
    int idx = blockIdx.x * blockDim.x + threadIdx.x;
    int d = idx & 63;
    int m = idx >> 10;
    int l = m & (SEQL - 1);
    int h = (idx >> 6) & (HEADS - 1);

    float e = (2.0f * (float)d) / 128.0f;
    float inv = 1.0f / powf(10000.0f, e);
    float ang = (float)l * inv;
    float s, c;
    sincosf(ang, &s, &c);

    size_t base = (size_t)m * HIDDEN + h * HD + d;
    float q1 = q[base], q2 = q[base + 64];
    float k1 = k[base], k2 = k[base + 64];
    float qa = q1 * c - q2 * s;
    float qb = q2 * c + q1 * s;
    float ka = k1 * c - k2 * s;
    float kb = k2 * c + k1 * s;

    __nv_bfloat16 t0;
    t0 = __float2bfloat16(qa); qh[base] = t0;      ql[base] = __float2bfloat16(qa - __bfloat162float(t0));
    t0 = __float2bfloat16(qb); qh[base + 64] = t0; ql[base + 64] = __float2bfloat16(qb - __bfloat162float(t0));
    t0 = __float2bfloat16(ka); kh[base] = t0;      kl[base] = __float2bfloat16(ka - __bfloat162float(t0));
    t0 = __float2bfloat16(kb); kh[base + 64] = t0; kl[base + 64] = __float2bfloat16(kb - __bfloat162float(t0));
}

// ---------------------------------------------------------------------------
// V transpose + round to single fp16
// ---------------------------------------------------------------------------
__global__ __launch_bounds__(256) void vt_half_kernel(
    const float* __restrict__ v, __half* __restrict__ vt)
{
    __shared__ float tile[32][33];
    const int bh = blockIdx.z;
    const int b = bh >> 4, h = bh & 15;
    const int l0 = blockIdx.x * 32, d0 = blockIdx.y * 32;
    const int tx = threadIdx.x, ty = threadIdx.y;

#pragma unroll
    for (int i = 0; i < 4; i++) {
        int r = ty + i * 8;
        tile[r][tx] = v[(size_t)(b * SEQL + l0 + r) * HIDDEN + h * HD + d0 + tx];
    }
    __syncthreads();
#pragma unroll
    for (int i = 0; i < 4; i++) {
        int r = ty + i * 8;
        size_t o = ((size_t)((b * HEADS + h) * HD + d0 + r)) * SEQL + l0 + tx;
        vt[o] = __float2half_rn(tile[tx][r]);
    }
}

// ---------------------------------------------------------------------------
// Flash attention: S = 3-term bf16; PV = 2-term fp16. (validated R12)
// ---------------------------------------------------------------------------
#define QW 136
#define VW 72
#define OQH 0
#define OQL 17408
#define OKH 34816
#define OKL 43520
#define OVH 52224
#define FLASH_SMEM ((52224 + 128 * VW) * 2) // 122880 bytes

__device__ __forceinline__ void pack_pair(float a, float b, uint32_t& hi_pack, uint32_t& lo_pack)
{
    __half2 h = __floats2half2_rn(a, b);
    hi_pack = *reinterpret_cast<uint32_t*>(&h);
    float ra = a - __half2float(__low2half(h));
    float rb = b - __half2float(__high2half(h));
    __half2 l = __floats2half2_rn(ra, rb);
    lo_pack = *reinterpret_cast<uint32_t*>(&l);
}

__global__ __launch_bounds__(256) void flash_mma_kernel(
    const __nv_bfloat16* __restrict__ Qh, const __nv_bfloat16* __restrict__ Ql,
    const __nv_bfloat16* __restrict__ Kh, const __nv_bfloat16* __restrict__ Kl,
    const __half* __restrict__ Vt16,
    float* __restrict__ O)
{
    extern __shared__ __nv_bfloat16 fs[];
    __nv_bfloat16* sQh = fs + OQH;
    __nv_bfloat16* sQl = fs + OQL;
    __nv_bfloat16* sKh = fs + OKH;
    __nv_bfloat16* sKl = fs + OKL;
    __half* sV = (__half*)(fs + OVH);

    const uint32_t fsU = (uint32_t)__cvta_generic_to_shared(fs);
    const uint32_t sQhU = fsU + OQH * 2;
    const uint32_t sQlU = fsU + OQL * 2;
    const uint32_t sKhU = fsU + OKH * 2;
    const uint32_t sKlU = fsU + OKL * 2;
    const uint32_t sVU = fsU + OVH * 2;

    const int qt = blockIdx.x, h = blockIdx.y, b = blockIdx.z;
    const int tid = threadIdx.x, lane = tid & 31, wid = tid >> 5;
    const int g = lane >> 2, t = lane & 3;
    const int lrow = lane & 15;
    const int lsel = (lane >> 4) * 8;
    const int wm = wid * 16;
    const float scale = 0.0883883476483184f;

    {
        const size_t base = (size_t)(b * SEQL + qt * 128) * HIDDEN + h * HD;
#pragma unroll
        for (int it = 0; it < 8; it++) {
            int id = tid + it * 256;
            int r = id >> 4, c8 = (id & 15) * 8;
            *(uint4*)&sQh[r * QW + c8] = *(const uint4*)&Qh[base + (size_t)r * HIDDEN + c8];
            *(uint4*)&sQl[r * QW + c8] = *(const uint4*)&Ql[base + (size_t)r * HIDDEN + c8];
        }
    }

    float m0 = -1e30f, m1 = -1e30f, l0 = 0.f, l1 = 0.f;
    float oacc[16][4];
#pragma unroll
    for (int nt = 0; nt < 16; nt++)
#pragma unroll
        for (int r = 0; r < 4; r++) oacc[nt][r] = 0.f;

    const int nkt = 2 * qt + 2;
    for (int kt = 0; kt < nkt; kt++) {
        __syncthreads();
#pragma unroll
        for (int it = 0; it < 4; it++) {
            int id = tid + it * 256;
            int r = id >> 4, c8 = (id & 15) * 8;
            size_t gk = (size_t)(b * SEQL + kt * 64 + r) * HIDDEN + h * HD + c8;
            *(uint4*)&sKh[r * QW + c8] = *(const uint4*)&Kh[gk];
            *(uint4*)&sKl[r * QW + c8] = *(const uint4*)&Kl[gk];
            int rv = id >> 3, cv = (id & 7) * 8;
            size_t gv = (size_t)((b * HEADS + h) * HD + rv) * SEQL + kt * 64 + cv;
            *(uint4*)&sV[rv * VW + cv] = *(const uint4*)&Vt16[gv];
        }
        __syncthreads();

        float sacc[8][4];
#pragma unroll
        for (int nt = 0; nt < 8; nt++)
#pragma unroll
            for (int r = 0; r < 4; r++) sacc[nt][r] = 0.f;

#pragma unroll
        for (int kc = 0; kc < 8; kc++) {
            const int kk = kc * 16;
            uint32_t aqh[4], aql[4];
            const uint32_t aoff = (uint32_t)((wm + lrow) * QW + kk + lsel) * 2;
            LDSM4(aqh[0], aqh[1], aqh[2], aqh[3], sQhU + aoff);
            LDSM4(aql[0], aql[1], aql[2], aql[3], sQlU + aoff);
            uint32_t bh[8][2], bl[8][2];
#pragma unroll
            for (int p = 0; p < 4; p++) {
                const uint32_t boff = (uint32_t)((p * 16 + lrow) * QW + kk + lsel) * 2;
                uint32_t r0, r1, r2, r3;
                LDSM4(r0, r1, r2, r3, sKhU + boff);
                bh[2 * p][0] = r0; bh[2 * p + 1][0] = r1;
                bh[2 * p][1] = r2; bh[2 * p + 1][1] = r3;
                LDSM4(r0, r1, r2, r3, sKlU + boff);
                bl[2 * p][0] = r0; bl[2 * p + 1][0] = r1;
                bl[2 * p][1] = r2; bl[2 * p + 1][1] = r3;
            }
#pragma unroll
            for (int nt = 0; nt < 8; nt++) {
                mma16816(sacc[nt], aqh, bh[nt]);
                mma16816(sacc[nt], aqh, bl[nt]);
                mma16816(sacc[nt], aql, bh[nt]);
            }
        }

        const int row0 = qt * 128 + wm + g;
        const int row1 = row0 + 8;
#pragma unroll
        for (int nt = 0; nt < 8; nt++) {
            sacc[nt][0] *= scale; sacc[nt][1] *= scale;
            sacc[nt][2] *= scale; sacc[nt][3] *= scale;
        }
        if (kt * 64 + 63 > qt * 128 + wm) {
#pragma unroll
            for (int nt = 0; nt < 8; nt++) {
                const int col = kt * 64 + nt * 8 + 2 * t;
                if (col > row0)     sacc[nt][0] = -1e30f;
                if (col + 1 > row0) sacc[nt][1] = -1e30f;
                if (col > row1)     sacc[nt][2] = -1e30f;
                if (col + 1 > row1) sacc[nt][3] = -1e30f;
            }
        }

        float mt0 = -1e30f, mt1 = -1e30f;
#pragma unroll
        for (int nt = 0; nt < 8; nt++) {
            mt0 = fmaxf(mt0, fmaxf(sacc[nt][0], sacc[nt][1]));
            mt1 = fmaxf(mt1, fmaxf(sacc[nt][2], sacc[nt][3]));
        }
        mt0 = fmaxf(mt0, __shfl_xor_sync(0xffffffffu, mt0, 1));
        mt0 = fmaxf(mt0, __shfl_xor_sync(0xffffffffu, mt0, 2));
        mt1 = fmaxf(mt1, __shfl_xor_sync(0xffffffffu, mt1, 1));
        mt1 = fmaxf(mt1, __shfl_xor_sync(0xffffffffu, mt1, 2));

        const float nm0 = fmaxf(m0, mt0), nm1 = fmaxf(m1, mt1);
        const float alpha0 = __expf(m0 - nm0), alpha1 = __expf(m1 - nm1);
        float ps0 = 0.f, ps1 = 0.f;
#pragma unroll
        for (int nt = 0; nt < 8; nt++) {
            sacc[nt][0] = __expf(sacc[nt][0] - nm0);
            sacc[nt][1] = __expf(sacc[nt][1] - nm0);
            sacc[nt][2] = __expf(sacc[nt][2] - nm1);
            sacc[nt][3] = __expf(sacc[nt][3] - nm1);
            ps0 += sacc[nt][0] + sacc[nt][1];
            ps1 += sacc[nt][2] + sacc[nt][3];
        }
        ps0 += __shfl_xor_sync(0xffffffffu, ps0, 1);
        ps0 += __shfl_xor_sync(0xffffffffu, ps0, 2);
        ps1 += __shfl_xor_sync(0xffffffffu, ps1, 1);
        ps1 += __shfl_xor_sync(0xffffffffu, ps1, 2);
        l0 = alpha0 * l0 + ps0; m0 = nm0;
        l1 = alpha1 * l1 + ps1; m1 = nm1;
#pragma unroll
        for (int nt = 0; nt < 16; nt++) {
            oacc[nt][0] *= alpha0; oacc[nt][1] *= alpha0;
            oacc[nt][2] *= alpha1; oacc[nt][3] *= alpha1;
        }

        uint32_t ph[4][4], pl[4][4];
#pragma unroll
        for (int kc = 0; kc < 4; kc++) {
            const int j0 = 2 * kc, j1 = 2 * kc + 1;
            pack_pair(sacc[j0][0], sacc[j0][1], ph[kc][0], pl[kc][0]);
            pack_pair(sacc[j0][2], sacc[j0][3], ph[kc][1], pl[kc][1]);
            pack_pair(sacc[j1][0], sacc[j1][1], ph[kc][2], pl[kc][2]);
            pack_pair(sacc[j1][2], sacc[j1][3], ph[kc][3], pl[kc][3]);
        }

#pragma unroll
        for (int kc = 0; kc < 4; kc++) {
#pragma unroll
            for (int p = 0; p < 8; p++) {
                const uint32_t voff = (uint32_t)((p * 16 + lrow) * VW + kc * 16 + lsel) * 2;
                uint32_t r0, r1, r2, r3;
                LDSM4(r0, r1, r2, r3, sVU + voff);
                uint32_t v0[2] = { r0, r2 };
                uint32_t v1[2] = { r1, r3 };
                mma16816h(oacc[2 * p], ph[kc], v0);
                mma16816h(oacc[2 * p], pl[kc], v0);
                mma16816h(oacc[2 * p + 1], ph[kc], v1);
                mma16816h(oacc[2 * p + 1], pl[kc], v1);
            }
        }
    }

    const float i0 = 1.0f / l0, i1 = 1.0f / l1;
    const size_t rbase = (size_t)(b * SEQL + qt * 128 + wm + g) * HIDDEN + h * HD + 2 * t;
#pragma unroll
    for (int nt = 0; nt < 16; nt++) {
        *(float2*)&O[rbase + nt * 8] = make_float2(oacc[nt][0] * i0, oacc[nt][1] * i0);
        *(float2*)&O[rbase + 8 * HIDDEN + nt * 8] = make_float2(oacc[nt][2] * i1, oacc[nt][3] * i1);
    }
}

// ---------------------------------------------------------------------------
extern "C" void kernel_launch(void* const* d_in, const int* in_sizes, int n_in,
                              void* d_out, int out_size)
{
    const float* x  = (const float*)d_in[0];
    const float* wq = (const float*)d_in[1];
    const float* wk = (const float*)d_in[2];
    const float* wv = (const float*)d_in[3];
    const float* wo = (const float*)d_in[4];
    float* out = (float*)d_out;

    float *q, *k, *v, *o;
    cudaGetSymbolAddress((void**)&q, g_q);
    cudaGetSymbolAddress((void**)&k, g_k);
    cudaGetSymbolAddress((void**)&v, g_v);
    cudaGetSymbolAddress((void**)&o, g_o);

    __nv_bfloat16 *qh, *ql, *kh, *kl;
    __half *xh16, *xl16, *oh16, *ol16, *wqh16, *wkh16, *wvh16, *woh16, *vt16;
    cudaGetSymbolAddress((void**)&qh, g_qh);
    cudaGetSymbolAddress((void**)&ql, g_ql);
    cudaGetSymbolAddress((void**)&kh, g_kh);
    cudaGetSymbolAddress((void**)&kl, g_kl);
    cudaGetSymbolAddress((void**)&xh16, g_xh16);
    cudaGetSymbolAddress((void**)&xl16, g_xl16);
    cudaGetSymbolAddress((void**)&oh16, g_oh16);
    cudaGetSymbolAddress((void**)&ol16, g_ol16);
    cudaGetSymbolAddress((void**)&wqh16, g_wqh16);
    cudaGetSymbolAddress((void**)&wkh16, g_wkh16);
    cudaGetSymbolAddress((void**)&wvh16, g_wvh16);
    cudaGetSymbolAddress((void**)&woh16, g_woh16);
    cudaGetSymbolAddress((void**)&vt16, g_vt16);

    const int nx4 = MROWS * HIDDEN / 4;
    const int nw4 = HIDDEN * HIDDEN / 4;
    split2h_kernel<<<(nx4 + 255) / 256, 256>>>((const float4*)x, xh16, xl16, nx4);
    round_h_kernel<<<(nw4 + 255) / 256, 256>>>((const float4*)wq, wqh16, nw4);
    round_h_kernel<<<(nw4 + 255) / 256, 256>>>((const float4*)wk, wkh16, nw4);
    round_h_kernel<<<(nw4 + 255) / 256, 256>>>((const float4*)wv, wvh16, nw4);
    round_h_kernel<<<(nw4 + 255) / 256, 256>>>((const float4*)wo, woh16, nw4);

    dim3 gg(HIDDEN / GBN, MROWS / GBM); // (16, 32)
    // QKV: one launch, fp16 2-pass, grid.z picks the weight/output set
    gemm2h_kernel<<<dim3(gg.x, gg.y, 3), 256>>>(
        xh16, xl16, wqh16, q, wkh16, k, wvh16, v);

    rope_split_kernel<<<(MROWS * HEADS * 64) / 256, 256>>>(q, k, qh, ql, kh, kl);
    vt_half_kernel<<<dim3(SEQL / 32, HD / 32, NBATCH * HEADS), dim3(32, 8)>>>(v, vt16);

    cudaFuncSetAttribute(flash_mma_kernel, cudaFuncAttributeMaxDynamicSharedMemorySize, FLASH_SMEM);
    flash_mma_kernel<<<dim3(SEQL / 128, HEADS, NBATCH), 256, FLASH_SMEM>>>(
        qh, ql, kh, kl, vt16, o);

    split2h_kernel<<<(nx4 + 255) / 256, 256>>>((const float4*)o, oh16, ol16, nx4);
    // O-projection: fp16 2-pass (z = 0 only)
    gemm2h_kernel<<<dim3(gg.x, gg.y, 1), 256>>>(
        oh16, ol16, woh16, out, woh16, out, woh16, out);
}

// round 15
// speedup vs baseline: 3.0168x; 1.5738x over previous
#include <cuda_runtime.h>
#include <cuda_bf16.h>
#include <cuda_fp16.h>
#include <math.h>
#include <stdint.h>

#define HIDDEN 2048
#define HEADS 16
#define HD 128
#define SEQL 2048
#define NBATCH 2
#define MROWS (NBATCH * SEQL) // 4096
#define KDIM 2048

// ---------------------------------------------------------------------------
// Scratch: __device__ globals (no cudaMalloc allowed)
// ---------------------------------------------------------------------------
__device__ float g_q[(size_t)MROWS * HIDDEN];
__device__ float g_k[(size_t)MROWS * HIDDEN];
__device__ float g_v[(size_t)MROWS * HIDDEN];
__device__ float g_o[(size_t)MROWS * HIDDEN];

// fp16 single-rounded operands (all projections)
__device__ __half g_x16[(size_t)MROWS * HIDDEN];
__device__ __half g_o16[(size_t)MROWS * HIDDEN];
__device__ __half g_wq16[(size_t)HIDDEN * HIDDEN];
__device__ __half g_wk16[(size_t)HIDDEN * HIDDEN];
__device__ __half g_wv16[(size_t)HIDDEN * HIDDEN];
__device__ __half g_wo16[(size_t)HIDDEN * HIDDEN];

// bf16 split Q/K (post-RoPE) and fp16 transposed V for flash
__device__ __nv_bfloat16 g_qh[(size_t)MROWS * HIDDEN];
__device__ __nv_bfloat16 g_ql[(size_t)MROWS * HIDDEN];
__device__ __nv_bfloat16 g_kh[(size_t)MROWS * HIDDEN];
__device__ __nv_bfloat16 g_kl[(size_t)MROWS * HIDDEN];
__device__ __half g_vt16[(size_t)MROWS * HIDDEN];

// ---------------------------------------------------------------------------
__device__ __forceinline__ void mma16816(float* c, const uint32_t* a, const uint32_t* b)
{
    asm volatile(
        "mma.sync.aligned.m16n8k16.row.col.f32.bf16.bf16.f32 "
        "{%0,%1,%2,%3}, {%4,%5,%6,%7}, {%8,%9}, {%0,%1,%2,%3};"
        : "+f"(c[0]), "+f"(c[1]), "+f"(c[2]), "+f"(c[3])
        : "r"(a[0]), "r"(a[1]), "r"(a[2]), "r"(a[3]), "r"(b[0]), "r"(b[1]));
}

__device__ __forceinline__ void mma16816h(float* c, const uint32_t* a, const uint32_t* b)
{
    asm volatile(
        "mma.sync.aligned.m16n8k16.row.col.f32.f16.f16.f32 "
        "{%0,%1,%2,%3}, {%4,%5,%6,%7}, {%8,%9}, {%0,%1,%2,%3};"
        : "+f"(c[0]), "+f"(c[1]), "+f"(c[2]), "+f"(c[3])
        : "r"(a[0]), "r"(a[1]), "r"(a[2]), "r"(a[3]), "r"(b[0]), "r"(b[1]));
}

#define LDSM4(r0, r1, r2, r3, addr) \
    asm volatile("ldmatrix.sync.aligned.m8n8.x4.shared.b16 {%0,%1,%2,%3}, [%4];" \
                 : "=r"(r0), "=r"(r1), "=r"(r2), "=r"(r3) : "r"(addr))

// ---------------------------------------------------------------------------
// Round fp32 -> fp16
// ---------------------------------------------------------------------------
__global__ void round_h_kernel(const float4* __restrict__ a,
                               __half* __restrict__ hi, int n4)
{
    int i = blockIdx.x * blockDim.x + threadIdx.x;
    if (i >= n4) return;
    float4 v = a[i];
    ushort4 hv;
    hv.x = __half_as_ushort(__float2half_rn(v.x));
    hv.y = __half_as_ushort(__float2half_rn(v.y));
    hv.z = __half_as_ushort(__float2half_rn(v.z));
    hv.w = __half_as_ushort(__float2half_rn(v.w));
    *(ushort4*)(hi + (size_t)i * 4) = hv;
}

// ---------------------------------------------------------------------------
// fp16 single-pass GEMM: C = A @ B^T. grid.z selects among up to 3 (B, C)
// sets sharing the same A (QKV in one launch).
// ---------------------------------------------------------------------------
#define GBM 128
#define GBN 128
#define GBK 32
#define LDS_W 40
#define TILE_B2 (GBM * LDS_W * 2)   // bytes per buffer = 10240
#define NCHUNK1 (KDIM / GBK)        // 64

__global__ __launch_bounds__(256) void gemm1h_kernel(
    const __half* __restrict__ A,
    const __half* __restrict__ Bh0, float* __restrict__ C0,
    const __half* __restrict__ Bh1, float* __restrict__ C1,
    const __half* __restrict__ Bh2, float* __restrict__ C2)
{
    const int z = blockIdx.z;
    const __half* Bh = (z == 0) ? Bh0 : (z == 1) ? Bh1 : Bh2;
    float* C = (z == 0) ? C0 : (z == 1) ? C1 : C2;

    __shared__ __half sA[2][GBM * LDS_W];
    __shared__ __half sB[2][GBN * LDS_W];

    const int tid = threadIdx.x;
    const int lane = tid & 31;
    const int wid = tid >> 5;
    const int wm = (wid & 3) * 32;
    const int wn = (wid >> 2) * 64;
    const int g = lane >> 2;
    const int t = lane & 3;
    const int lrow = lane & 15;
    const int lsel = (lane >> 4) * 8;

    const int bm = blockIdx.y * GBM;
    const int bn = blockIdx.x * GBN;

    const int grow = tid >> 1;
    const int gcol = (tid & 1) * 16;

    const uint32_t sAu = (uint32_t)__cvta_generic_to_shared(&sA[0][0]);
    const uint32_t sBu = (uint32_t)__cvta_generic_to_shared(&sB[0][0]);

    float acc[2][8][4];
#pragma unroll
    for (int i = 0; i < 2; i++)
#pragma unroll
        for (int j = 0; j < 8; j++)
#pragma unroll
            for (int r = 0; r < 4; r++) acc[i][j][r] = 0.f;

    auto fetch = [&](int c, uint4& ra0, uint4& ra1, uint4& rb0, uint4& rb1) {
        const int k0 = c * GBK;
        const size_t ga = (size_t)(bm + grow) * KDIM + k0 + gcol;
        const size_t gb = (size_t)(bn + grow) * KDIM + k0 + gcol;
        ra0 = *(const uint4*)(A + ga);
        ra1 = *(const uint4*)(A + ga + 8);
        rb0 = *(const uint4*)(Bh + gb);
        rb1 = *(const uint4*)(Bh + gb + 8);
    };
    auto store = [&](int buf, const uint4& ra0, const uint4& ra1,
                     const uint4& rb0, const uint4& rb1) {
        __half* pa = &sA[buf][grow * LDS_W + gcol];
        __half* pb = &sB[buf][grow * LDS_W + gcol];
        *(uint4*)pa = ra0;
        *(uint4*)(pa + 8) = ra1;
        *(uint4*)pb = rb0;
        *(uint4*)(pb + 8) = rb1;
    };

    {
        uint4 ra0, ra1, rb0, rb1;
        fetch(0, ra0, ra1, rb0, rb1);
        store(0, ra0, ra1, rb0, rb1);
    }
    __syncthreads();

    for (int c = 0; c < NCHUNK1; c++) {
        const int buf = c & 1;
        const bool more = (c + 1 < NCHUNK1);
        uint4 ra0, ra1, rb0, rb1;
        if (more) fetch(c + 1, ra0, ra1, rb0, rb1);

        const uint32_t sa = sAu + (uint32_t)buf * TILE_B2;
        const uint32_t sb = sBu + (uint32_t)buf * TILE_B2;
#pragma unroll
        for (int kk = 0; kk < GBK; kk += 16) {
            uint32_t af[2][4];
#pragma unroll
            for (int mt = 0; mt < 2; mt++) {
                const uint32_t ra = sa + (uint32_t)((wm + mt * 16 + lrow) * LDS_W + kk + lsel) * 2;
                LDSM4(af[mt][0], af[mt][1], af[mt][2], af[mt][3], ra);
            }
            uint32_t bfr[8][2];
#pragma unroll
            for (int p = 0; p < 4; p++) {
                const uint32_t rb = sb + (uint32_t)((wn + p * 16 + lrow) * LDS_W + kk + lsel) * 2;
                uint32_t r0, r1, r2, r3;
                LDSM4(r0, r1, r2, r3, rb);
                bfr[2 * p][0] = r0; bfr[2 * p + 1][0] = r1;
                bfr[2 * p][1] = r2; bfr[2 * p + 1][1] = r3;
            }
#pragma unroll
            for (int mt = 0; mt < 2; mt++)
#pragma unroll
                for (int nt = 0; nt < 8; nt++)
                    mma16816h(acc[mt][nt], af[mt], bfr[nt]);
        }

        if (more) store(buf ^ 1, ra0, ra1, rb0, rb1);
        __syncthreads();
    }

#pragma unroll
    for (int mt = 0; mt < 2; mt++) {
        const int r0 = bm + wm + mt * 16 + g;
#pragma unroll
        for (int nt = 0; nt < 8; nt++) {
            const int col = bn + wn + nt * 8 + 2 * t;
            *(float2*)&C[(size_t)r0 * HIDDEN + col] = make_float2(acc[mt][nt][0], acc[mt][nt][1]);
            *(float2*)&C[(size_t)(r0 + 8) * HIDDEN + col] = make_float2(acc[mt][nt][2], acc[mt][nt][3]);
        }
    }
}

// ---------------------------------------------------------------------------
// RoPE + split to bf16 hi/lo for Q and K (flash softmax path stays bf16 x3).
// ---------------------------------------------------------------------------
__global__ void rope_split_kernel(const float* __restrict__ q, const float* __restrict__ k,
                                  __nv_bfloat16* __restrict__ qh, __nv_bfloat16* __restrict__ ql,
                                  __nv_bfloat16* __restrict__ kh, __nv_bfloat16* __restrict__ kl)
{
    int idx = blockIdx.x * blockDim.x + threadIdx.x;
    int d = idx & 63;
    int m = idx >> 10;
    int l = m & (SEQL - 1);
    int h = (idx >> 6) & (HEADS - 1);

    float e = (2.0f * (float)d) / 128.0f;
    float inv = 1.0f / powf(10000.0f, e);
    float ang = (float)l * inv;
    float s, c;
    sincosf(ang, &s, &c);

    size_t base = (size_t)m * HIDDEN + h * HD + d;
    float q1 = q[base], q2 = q[base + 64];
    float k1 = k[base], k2 = k[base + 64];
    float qa = q1 * c - q2 * s;
    float qb = q2 * c + q1 * s;
    float ka = k1 * c - k2 * s;
    float kb = k2 * c + k1 * s;

    __nv_bfloat16 t0;
    t0 = __float2bfloat16(qa); qh[base] = t0;      ql[base] = __float2bfloat16(qa - __bfloat162float(t0));
    t0 = __float2bfloat16(qb); qh[base + 64] = t0; ql[base + 64] = __float2bfloat16(qb - __bfloat162float(t0));
    t0 = __float2bfloat16(ka); kh[base] = t0;      kl[base] = __float2bfloat16(ka - __bfloat162float(t0));
    t0 = __float2bfloat16(kb); kh[base + 64] = t0; kl[base + 64] = __float2bfloat16(kb - __bfloat162float(t0));
}

// ---------------------------------------------------------------------------
// V transpose + round to single fp16
// ---------------------------------------------------------------------------
__global__ __launch_bounds__(256) void vt_half_kernel(
    const float* __restrict__ v, __half* __restrict__ vt)
{
    __shared__ float tile[32][33];
    const int bh = blockIdx.z;
    const int b = bh >> 4, h = bh & 15;
    const int l0 = blockIdx.x * 32, d0 = blockIdx.y * 32;
    const int tx = threadIdx.x, ty = threadIdx.y;

#pragma unroll
    for (int i = 0; i < 4; i++) {
        int r = ty + i * 8;
        tile[r][tx] = v[(size_t)(b * SEQL + l0 + r) * HIDDEN + h * HD + d0 + tx];
    }
    __syncthreads();
#pragma unroll
    for (int i = 0; i < 4; i++) {
        int r = ty + i * 8;
        size_t o = ((size_t)((b * HEADS + h) * HD + d0 + r)) * SEQL + l0 + tx;
        vt[o] = __float2half_rn(tile[tx][r]);
    }
}

// ---------------------------------------------------------------------------
// Flash attention: S = 3-term bf16; PV = 2-term fp16. (validated R12)
// ---------------------------------------------------------------------------
#define QW 136
#define VW 72
#define OQH 0
#define OQL 17408
#define OKH 34816
#define OKL 43520
#define OVH 52224
#define FLASH_SMEM ((52224 + 128 * VW) * 2) // 122880 bytes

__device__ __forceinline__ void pack_pair(float a, float b, uint32_t& hi_pack, uint32_t& lo_pack)
{
    __half2 h = __floats2half2_rn(a, b);
    hi_pack = *reinterpret_cast<uint32_t*>(&h);
    float ra = a - __half2float(__low2half(h));
    float rb = b - __half2float(__high2half(h));
    __half2 l = __floats2half2_rn(ra, rb);
    lo_pack = *reinterpret_cast<uint32_t*>(&l);
}

__global__ __launch_bounds__(256) void flash_mma_kernel(
    const __nv_bfloat16* __restrict__ Qh, const __nv_bfloat16* __restrict__ Ql,
    const __nv_bfloat16* __restrict__ Kh, const __nv_bfloat16* __restrict__ Kl,
    const __half* __restrict__ Vt16,
    float* __restrict__ O)
{
    extern __shared__ __nv_bfloat16 fs[];
    __nv_bfloat16* sQh = fs + OQH;
    __nv_bfloat16* sQl = fs + OQL;
    __nv_bfloat16* sKh = fs + OKH;
    __nv_bfloat16* sKl = fs + OKL;
    __half* sV = (__half*)(fs + OVH);

    const uint32_t fsU = (uint32_t)__cvta_generic_to_shared(fs);
    const uint32_t sQhU = fsU + OQH * 2;
    const uint32_t sQlU = fsU + OQL * 2;
    const uint32_t sKhU = fsU + OKH * 2;
    const uint32_t sKlU = fsU + OKL * 2;
    const uint32_t sVU = fsU + OVH * 2;

    const int qt = blockIdx.x, h = blockIdx.y, b = blockIdx.z;
    const int tid = threadIdx.x, lane = tid & 31, wid = tid >> 5;
    const int g = lane >> 2, t = lane & 3;
    const int lrow = lane & 15;
    const int lsel = (lane >> 4) * 8;
    const int wm = wid * 16;
    const float scale = 0.0883883476483184f;

    {
        const size_t base = (size_t)(b * SEQL + qt * 128) * HIDDEN + h * HD;
#pragma unroll
        for (int it = 0; it < 8; it++) {
            int id = tid + it * 256;
            int r = id >> 4, c8 = (id & 15) * 8;
            *(uint4*)&sQh[r * QW + c8] = *(const uint4*)&Qh[base + (size_t)r * HIDDEN + c8];
            *(uint4*)&sQl[r * QW + c8] = *(const uint4*)&Ql[base + (size_t)r * HIDDEN + c8];
        }
    }

    float m0 = -1e30f, m1 = -1e30f, l0 = 0.f, l1 = 0.f;
    float oacc[16][4];
#pragma unroll
    for (int nt = 0; nt < 16; nt++)
#pragma unroll
        for (int r = 0; r < 4; r++) oacc[nt][r] = 0.f;

    const int nkt = 2 * qt + 2;
    for (int kt = 0; kt < nkt; kt++) {
        __syncthreads();
#pragma unroll
        for (int it = 0; it < 4; it++) {
            int id = tid + it * 256;
            int r = id >> 4, c8 = (id & 15) * 8;
            size_t gk = (size_t)(b * SEQL + kt * 64 + r) * HIDDEN + h * HD + c8;
            *(uint4*)&sKh[r * QW + c8] = *(const uint4*)&Kh[gk];
            *(uint4*)&sKl[r * QW + c8] = *(const uint4*)&Kl[gk];
            int rv = id >> 3, cv = (id & 7) * 8;
            size_t gv = (size_t)((b * HEADS + h) * HD + rv) * SEQL + kt * 64 + cv;
            *(uint4*)&sV[rv * VW + cv] = *(const uint4*)&Vt16[gv];
        }
        __syncthreads();

        float sacc[8][4];
#pragma unroll
        for (int nt = 0; nt < 8; nt++)
#pragma unroll
            for (int r = 0; r < 4; r++) sacc[nt][r] = 0.f;

#pragma unroll
        for (int kc = 0; kc < 8; kc++) {
            const int kk = kc * 16;
            uint32_t aqh[4], aql[4];
            const uint32_t aoff = (uint32_t)((wm + lrow) * QW + kk + lsel) * 2;
            LDSM4(aqh[0], aqh[1], aqh[2], aqh[3], sQhU + aoff);
            LDSM4(aql[0], aql[1], aql[2], aql[3], sQlU + aoff);
            uint32_t bh[8][2], bl[8][2];
#pragma unroll
            for (int p = 0; p < 4; p++) {
                const uint32_t boff = (uint32_t)((p * 16 + lrow) * QW + kk + lsel) * 2;
                uint32_t r0, r1, r2, r3;
                LDSM4(r0, r1, r2, r3, sKhU + boff);
                bh[2 * p][0] = r0; bh[2 * p + 1][0] = r1;
                bh[2 * p][1] = r2; bh[2 * p + 1][1] = r3;
                LDSM4(r0, r1, r2, r3, sKlU + boff);
                bl[2 * p][0] = r0; bl[2 * p + 1][0] = r1;
                bl[2 * p][1] = r2; bl[2 * p + 1][1] = r3;
            }
#pragma unroll
            for (int nt = 0; nt < 8; nt++) {
                mma16816(sacc[nt], aqh, bh[nt]);
                mma16816(sacc[nt], aqh, bl[nt]);
                mma16816(sacc[nt], aql, bh[nt]);
            }
        }

        const int row0 = qt * 128 + wm + g;
        const int row1 = row0 + 8;
#pragma unroll
        for (int nt = 0; nt < 8; nt++) {
            sacc[nt][0] *= scale; sacc[nt][1] *= scale;
            sacc[nt][2] *= scale; sacc[nt][3] *= scale;
        }
        if (kt * 64 + 63 > qt * 128 + wm) {
#pragma unroll
            for (int nt = 0; nt < 8; nt++) {
                const int col = kt * 64 + nt * 8 + 2 * t;
                if (col > row0)     sacc[nt][0] = -1e30f;
                if (col + 1 > row0) sacc[nt][1] = -1e30f;
                if (col > row1)     sacc[nt][2] = -1e30f;
                if (col + 1 > row1) sacc[nt][3] = -1e30f;
            }
        }

        float mt0 = -1e30f, mt1 = -1e30f;
#pragma unroll
        for (int nt = 0; nt < 8; nt++) {
            mt0 = fmaxf(mt0, fmaxf(sacc[nt][0], sacc[nt][1]));
            mt1 = fmaxf(mt1, fmaxf(sacc[nt][2], sacc[nt][3]));
        }
        mt0 = fmaxf(mt0, __shfl_xor_sync(0xffffffffu, mt0, 1));
        mt0 = fmaxf(mt0, __shfl_xor_sync(0xffffffffu, mt0, 2));
        mt1 = fmaxf(mt1, __shfl_xor_sync(0xffffffffu, mt1, 1));
        mt1 = fmaxf(mt1, __shfl_xor_sync(0xffffffffu, mt1, 2));

        const float nm0 = fmaxf(m0, mt0), nm1 = fmaxf(m1, mt1);
        const float alpha0 = __expf(m0 - nm0), alpha1 = __expf(m1 - nm1);
        float ps0 = 0.f, ps1 = 0.f;
#pragma unroll
        for (int nt = 0; nt < 8; nt++) {
            sacc[nt][0] = __expf(sacc[nt][0] - nm0);
            sacc[nt][1] = __expf(sacc[nt][1] - nm0);
            sacc[nt][2] = __expf(sacc[nt][2] - nm1);
            sacc[nt][3] = __expf(sacc[nt][3] - nm1);
            ps0 += sacc[nt][0] + sacc[nt][1];
            ps1 += sacc[nt][2] + sacc[nt][3];
        }
        ps0 += __shfl_xor_sync(0xffffffffu, ps0, 1);
        ps0 += __shfl_xor_sync(0xffffffffu, ps0, 2);
        ps1 += __shfl_xor_sync(0xffffffffu, ps1, 1);
        ps1 += __shfl_xor_sync(0xffffffffu, ps1, 2);
        l0 = alpha0 * l0 + ps0; m0 = nm0;
        l1 = alpha1 * l1 + ps1; m1 = nm1;
#pragma unroll
        for (int nt = 0; nt < 16; nt++) {
            oacc[nt][0] *= alpha0; oacc[nt][1] *= alpha0;
            oacc[nt][2] *= alpha1; oacc[nt][3] *= alpha1;
        }

        uint32_t ph[4][4], pl[4][4];
#pragma unroll
        for (int kc = 0; kc < 4; kc++) {
            const int j0 = 2 * kc, j1 = 2 * kc + 1;
            pack_pair(sacc[j0][0], sacc[j0][1], ph[kc][0], pl[kc][0]);
            pack_pair(sacc[j0][2], sacc[j0][3], ph[kc][1], pl[kc][1]);
            pack_pair(sacc[j1][0], sacc[j1][1], ph[kc][2], pl[kc][2]);
            pack_pair(sacc[j1][2], sacc[j1][3], ph[kc][3], pl[kc][3]);
        }

#pragma unroll
        for (int kc = 0; kc < 4; kc++) {
#pragma unroll
            for (int p = 0; p < 8; p++) {
                const uint32_t voff = (uint32_t)((p * 16 + lrow) * VW + kc * 16 + lsel) * 2;
                uint32_t r0, r1, r2, r3;
                LDSM4(r0, r1, r2, r3, sVU + voff);
                uint32_t v0[2] = { r0, r2 };
                uint32_t v1[2] = { r1, r3 };
                mma16816h(oacc[2 * p], ph[kc], v0);
                mma16816h(oacc[2 * p], pl[kc], v0);
                mma16816h(oacc[2 * p + 1], ph[kc], v1);
                mma16816h(oacc[2 * p + 1], pl[kc], v1);
            }
        }
    }

    const float i0 = 1.0f / l0, i1 = 1.0f / l1;
    const size_t rbase = (size_t)(b * SEQL + qt * 128 + wm + g) * HIDDEN + h * HD + 2 * t;
#pragma unroll
    for (int nt = 0; nt < 16; nt++) {
        *(float2*)&O[rbase + nt * 8] = make_float2(oacc[nt][0] * i0, oacc[nt][1] * i0);
        *(float2*)&O[rbase + 8 * HIDDEN + nt * 8] = make_float2(oacc[nt][2] * i1, oacc[nt][3] * i1);
    }
}

// ---------------------------------------------------------------------------
extern "C" void kernel_launch(void* const* d_in, const int* in_sizes, int n_in,
                              void* d_out, int out_size)
{
    const float* x  = (const float*)d_in[0];
    const float* wq = (const float*)d_in[1];
    const float* wk = (const float*)d_in[2];
    const float* wv = (const float*)d_in[3];
    const float* wo = (const float*)d_in[4];
    float* out = (float*)d_out;

    float *q, *k, *v, *o;
    cudaGetSymbolAddress((void**)&q, g_q);
    cudaGetSymbolAddress((void**)&k, g_k);
    cudaGetSymbolAddress((void**)&v, g_v);
    cudaGetSymbolAddress((void**)&o, g_o);

    __nv_bfloat16 *qh, *ql, *kh, *kl;
    __half *x16, *o16, *wq16, *wk16, *wv16, *wo16, *vt16;
    cudaGetSymbolAddress((void**)&qh, g_qh);
    cudaGetSymbolAddress((void**)&ql, g_ql);
    cudaGetSymbolAddress((void**)&kh, g_kh);
    cudaGetSymbolAddress((void**)&kl, g_kl);
    cudaGetSymbolAddress((void**)&x16, g_x16);
    cudaGetSymbolAddress((void**)&o16, g_o16);
    cudaGetSymbolAddress((void**)&wq16, g_wq16);
    cudaGetSymbolAddress((void**)&wk16, g_wk16);
    cudaGetSymbolAddress((void**)&wv16, g_wv16);
    cudaGetSymbolAddress((void**)&wo16, g_wo16);
    cudaGetSymbolAddress((void**)&vt16, g_vt16);

    const int nx4 = MROWS * HIDDEN / 4;
    const int nw4 = HIDDEN * HIDDEN / 4;
    round_h_kernel<<<(nx4 + 255) / 256, 256>>>((const float4*)x, x16, nx4);
    round_h_kernel<<<(nw4 + 255) / 256, 256>>>((const float4*)wq, wq16, nw4);
    round_h_kernel<<<(nw4 + 255) / 256, 256>>>((const float4*)wk, wk16, nw4);
    round_h_kernel<<<(nw4 + 255) / 256, 256>>>((const float4*)wv, wv16, nw4);
    round_h_kernel<<<(nw4 + 255) / 256, 256>>>((const float4*)wo, wo16, nw4);

    dim3 gg(HIDDEN / GBN, MROWS / GBM); // (16, 32)
    // QKV: one launch, fp16 single-pass, grid.z picks the weight/output set
    gemm1h_kernel<<<dim3(gg.x, gg.y, 3), 256>>>(
        x16, wq16, q, wk16, k, wv16, v);

    rope_split_kernel<<<(MROWS * HEADS * 64) / 256, 256>>>(q, k, qh, ql, kh, kl);
    vt_half_kernel<<<dim3(SEQL / 32, HD / 32, NBATCH * HEADS), dim3(32, 8)>>>(v, vt16);

    cudaFuncSetAttribute(flash_mma_kernel, cudaFuncAttributeMaxDynamicSharedMemorySize, FLASH_SMEM);
    flash_mma_kernel<<<dim3(SEQL / 128, HEADS, NBATCH), 256, FLASH_SMEM>>>(
        qh, ql, kh, kl, vt16, o);

    round_h_kernel<<<(nx4 + 255) / 256, 256>>>((const float4*)o, o16, nx4);
    // O-projection: fp16 single-pass (z = 0 only)
    gemm1h_kernel<<<dim3(gg.x, gg.y, 1), 256>>>(
        o16, wo16, out, wo16, out, wo16, out);
}